// round 4
// baseline (speedup 1.0000x reference)
#include <cuda_runtime.h>

#define NB    16384
#define NS    37
#define NF    17
#define NOWN  9
#define NH    256
#define NE    128
#define NCAT  137
#define NOUT  23

// scratch: concatenated [summed(128) | s_own(9)] per batch row
__device__ float g_cat[(size_t)NB * NCAT];

// ---------------------------------------------------------------------------
// Kernel A: per-batch token MLP (17->256->256->128), masked sum over tokens
// ---------------------------------------------------------------------------
struct SmemA {
    float hbuf[NS * NH];   // 37*256 activations (layer1 out, then layer2 out)
    float wT[NH * 36];     // transposed weight chunk, stride 36 (16B-aligned, conflict-free)
    float xs[NS * NF];     // token inputs
    float maskv[NS];
    float part[NE];        // cross-half partial sums for layer3
};

__global__ __launch_bounds__(256, 2) void embed_kernel(
    const float* __restrict__ obs,
    const float* __restrict__ sW1, const float* __restrict__ sb1,
    const float* __restrict__ sW2, const float* __restrict__ sb2,
    const float* __restrict__ sW3, const float* __restrict__ sb3)
{
    extern __shared__ char smraw[];
    SmemA& sm = *reinterpret_cast<SmemA*>(smraw);
    const int b = blockIdx.x;
    const int t = threadIdx.x;
    const float* ob = obs + (size_t)b * (NS + 1) * NF;

    // load token rows 1..37
    for (int idx = t; idx < NS * NF; idx += 256)
        sm.xs[idx] = ob[NF + idx];
    __syncthreads();
    if (t < NS) {
        float sabs = 0.f;
        #pragma unroll
        for (int k = 0; k < NF; k++) sabs += fabsf(sm.xs[t * NF + k]);
        sm.maskv[t] = (sabs != 0.f) ? 1.f : 0.f;
    }

    // ---- layer 1: thread t owns output column t ----
    float w1c[NF];
    #pragma unroll
    for (int k = 0; k < NF; k++) w1c[k] = sW1[k * NH + t];
    const float b1 = sb1[t];
    #pragma unroll 1
    for (int i = 0; i < NS; i++) {
        float a = b1;
        #pragma unroll
        for (int k = 0; k < NF; k++) a = fmaf(sm.xs[i * NF + k], w1c[k], a);
        sm.hbuf[i * NH + t] = fmaxf(a, 0.f);
    }

    // ---- layer 2: 256x256, K chunked by 32 through smem ----
    float acc2[NS];
    #pragma unroll
    for (int i = 0; i < NS; i++) acc2[i] = 0.f;
    #pragma unroll 1
    for (int kc = 0; kc < NH; kc += 32) {
        __syncthreads();
        for (int idx = t; idx < 32 * NH; idx += 256) {
            int kk = idx >> 8;
            int j  = idx & 255;
            sm.wT[j * 36 + kk] = sW2[(kc + kk) * NH + j];
        }
        __syncthreads();
        #pragma unroll
        for (int kk = 0; kk < 32; kk += 4) {
            float4 w = *(const float4*)&sm.wT[t * 36 + kk];
            #pragma unroll
            for (int i = 0; i < NS; i++) {
                float4 hv = *(const float4*)&sm.hbuf[i * NH + kc + kk];
                acc2[i] = fmaf(hv.x, w.x, acc2[i]);
                acc2[i] = fmaf(hv.y, w.y, acc2[i]);
                acc2[i] = fmaf(hv.z, w.z, acc2[i]);
                acc2[i] = fmaf(hv.w, w.w, acc2[i]);
            }
        }
    }
    __syncthreads();
    {
        const float b2 = sb2[t];
        #pragma unroll 1
        for (int i = 0; i < NS; i++)
            sm.hbuf[i * NH + t] = fmaxf(acc2[i] + b2, 0.f);
    }

    // ---- layer 3: 256x128; rows split across block halves ----
    const int g  = t >> 7;
    const int j3 = t & 127;
    const int i0 = g ? 19 : 0;
    float acc3[19];
    #pragma unroll
    for (int i = 0; i < 19; i++) acc3[i] = 0.f;
    #pragma unroll 1
    for (int kc = 0; kc < NH; kc += 32) {
        __syncthreads();
        for (int idx = t; idx < 32 * NE; idx += 256) {
            int kk = idx >> 7;
            int j  = idx & 127;
            sm.wT[j * 36 + kk] = sW3[(kc + kk) * NE + j];
        }
        __syncthreads();
        #pragma unroll
        for (int kk = 0; kk < 32; kk += 4) {
            float4 w = *(const float4*)&sm.wT[j3 * 36 + kk];
            #pragma unroll
            for (int i = 0; i < 19; i++) {
                int ri = i0 + i;
                if (ri < NS) {
                    float4 hv = *(const float4*)&sm.hbuf[ri * NH + kc + kk];
                    acc3[i] = fmaf(hv.x, w.x, acc3[i]);
                    acc3[i] = fmaf(hv.y, w.y, acc3[i]);
                    acc3[i] = fmaf(hv.z, w.z, acc3[i]);
                    acc3[i] = fmaf(hv.w, w.w, acc3[i]);
                }
            }
        }
    }
    {
        const float b3 = sb3[j3];
        float lsum = 0.f;
        #pragma unroll
        for (int i = 0; i < 19; i++) {
            int ri = i0 + i;
            if (ri < NS) lsum += sm.maskv[ri] * fmaxf(acc3[i] + b3, 0.f);
        }
        if (g == 1) sm.part[j3] = lsum;
        __syncthreads();
        if (g == 0)
            g_cat[(size_t)b * NCAT + j3] = lsum + sm.part[j3];
    }
    if (t < NOWN)
        g_cat[(size_t)b * NCAT + NE + t] = ob[t];
}

// ---------------------------------------------------------------------------
// Kernel B: action/value heads, 32 batch rows per CTA
// ---------------------------------------------------------------------------
struct SmemB {
    float cats[32 * 160];  // cat inputs, padded 137 -> 160 (zero pad)
    float ha[32 * NH];     // hidden activations (reused across layers/branches)
    float wT[NH * 36];     // transposed weight chunk
};

__global__ __launch_bounds__(256, 2) void heads_kernel(
    float* __restrict__ out,
    const float* __restrict__ aW1, const float* __restrict__ ab1,
    const float* __restrict__ aW2, const float* __restrict__ ab2,
    const float* __restrict__ aW3, const float* __restrict__ ab3,
    const float* __restrict__ vW1, const float* __restrict__ vb1,
    const float* __restrict__ vW2, const float* __restrict__ vb2,
    const float* __restrict__ vW3, const float* __restrict__ vb3)
{
    extern __shared__ char smraw[];
    SmemB& sm = *reinterpret_cast<SmemB*>(smraw);
    const int t  = threadIdx.x;
    const int rb = blockIdx.x * 32;

    for (int idx = t; idx < 32 * 160; idx += 256) {
        int r = idx / 160, c = idx % 160;
        sm.cats[idx] = (c < NCAT) ? g_cat[(size_t)(rb + r) * NCAT + c] : 0.f;
    }

    float acc[32];

    // ========== branch a ==========
    #pragma unroll
    for (int r = 0; r < 32; r++) acc[r] = 0.f;
    #pragma unroll 1
    for (int kc = 0; kc < 160; kc += 32) {
        __syncthreads();
        for (int idx = t; idx < 32 * NH; idx += 256) {
            int kk = idx >> 8, j = idx & 255;
            int k = kc + kk;
            sm.wT[j * 36 + kk] = (k < NCAT) ? aW1[k * NH + j] : 0.f;
        }
        __syncthreads();
        #pragma unroll
        for (int kk = 0; kk < 32; kk += 4) {
            float4 w = *(const float4*)&sm.wT[t * 36 + kk];
            #pragma unroll
            for (int r = 0; r < 32; r++) {
                float4 cv = *(const float4*)&sm.cats[r * 160 + kc + kk];
                acc[r] = fmaf(cv.x, w.x, acc[r]);
                acc[r] = fmaf(cv.y, w.y, acc[r]);
                acc[r] = fmaf(cv.z, w.z, acc[r]);
                acc[r] = fmaf(cv.w, w.w, acc[r]);
            }
        }
    }
    __syncthreads();
    {
        const float bb = ab1[t];
        #pragma unroll 1
        for (int r = 0; r < 32; r++) sm.ha[r * NH + t] = fmaxf(acc[r] + bb, 0.f);
    }

    #pragma unroll
    for (int r = 0; r < 32; r++) acc[r] = 0.f;
    #pragma unroll 1
    for (int kc = 0; kc < NH; kc += 32) {
        __syncthreads();
        for (int idx = t; idx < 32 * NH; idx += 256) {
            int kk = idx >> 8, j = idx & 255;
            sm.wT[j * 36 + kk] = aW2[(kc + kk) * NH + j];
        }
        __syncthreads();
        #pragma unroll
        for (int kk = 0; kk < 32; kk += 4) {
            float4 w = *(const float4*)&sm.wT[t * 36 + kk];
            #pragma unroll
            for (int r = 0; r < 32; r++) {
                float4 hv = *(const float4*)&sm.ha[r * NH + kc + kk];
                acc[r] = fmaf(hv.x, w.x, acc[r]);
                acc[r] = fmaf(hv.y, w.y, acc[r]);
                acc[r] = fmaf(hv.z, w.z, acc[r]);
                acc[r] = fmaf(hv.w, w.w, acc[r]);
            }
        }
    }
    __syncthreads();
    {
        const float bb = ab2[t];
        #pragma unroll 1
        for (int r = 0; r < 32; r++) sm.ha[r * NH + t] = fmaxf(acc[r] + bb, 0.f);
    }
    __syncthreads();

    // a3: 23 logits x 32 rows
    for (int idx = t; idx < 32 * NOUT; idx += 256) {
        int r = idx / NOUT, c = idx - r * NOUT;
        float a = ab3[c];
        #pragma unroll 4
        for (int k = 0; k < NH; k += 4) {
            float4 hv = *(const float4*)&sm.ha[r * NH + k];
            a = fmaf(hv.x, aW3[(k + 0) * NOUT + c], a);
            a = fmaf(hv.y, aW3[(k + 1) * NOUT + c], a);
            a = fmaf(hv.z, aW3[(k + 2) * NOUT + c], a);
            a = fmaf(hv.w, aW3[(k + 3) * NOUT + c], a);
        }
        out[(size_t)(rb + r) * NOUT + c] = a;
    }
    __syncthreads();  // a3 done reading ha before v branch overwrites it

    // ========== branch v ==========
    #pragma unroll
    for (int r = 0; r < 32; r++) acc[r] = 0.f;
    #pragma unroll 1
    for (int kc = 0; kc < 160; kc += 32) {
        __syncthreads();
        for (int idx = t; idx < 32 * NH; idx += 256) {
            int kk = idx >> 8, j = idx & 255;
            int k = kc + kk;
            sm.wT[j * 36 + kk] = (k < NCAT) ? vW1[k * NH + j] : 0.f;
        }
        __syncthreads();
        #pragma unroll
        for (int kk = 0; kk < 32; kk += 4) {
            float4 w = *(const float4*)&sm.wT[t * 36 + kk];
            #pragma unroll
            for (int r = 0; r < 32; r++) {
                float4 cv = *(const float4*)&sm.cats[r * 160 + kc + kk];
                acc[r] = fmaf(cv.x, w.x, acc[r]);
                acc[r] = fmaf(cv.y, w.y, acc[r]);
                acc[r] = fmaf(cv.z, w.z, acc[r]);
                acc[r] = fmaf(cv.w, w.w, acc[r]);
            }
        }
    }
    __syncthreads();
    {
        const float bb = vb1[t];
        #pragma unroll 1
        for (int r = 0; r < 32; r++) sm.ha[r * NH + t] = fmaxf(acc[r] + bb, 0.f);
    }

    #pragma unroll
    for (int r = 0; r < 32; r++) acc[r] = 0.f;
    #pragma unroll 1
    for (int kc = 0; kc < NH; kc += 32) {
        __syncthreads();
        for (int idx = t; idx < 32 * NH; idx += 256) {
            int kk = idx >> 8, j = idx & 255;
            sm.wT[j * 36 + kk] = vW2[(kc + kk) * NH + j];
        }
        __syncthreads();
        #pragma unroll
        for (int kk = 0; kk < 32; kk += 4) {
            float4 w = *(const float4*)&sm.wT[t * 36 + kk];
            #pragma unroll
            for (int r = 0; r < 32; r++) {
                float4 hv = *(const float4*)&sm.ha[r * NH + kc + kk];
                acc[r] = fmaf(hv.x, w.x, acc[r]);
                acc[r] = fmaf(hv.y, w.y, acc[r]);
                acc[r] = fmaf(hv.z, w.z, acc[r]);
                acc[r] = fmaf(hv.w, w.w, acc[r]);
            }
        }
    }
    __syncthreads();
    {
        const float bb = vb2[t];
        #pragma unroll 1
        for (int r = 0; r < 32; r++) sm.ha[r * NH + t] = fmaxf(acc[r] + bb, 0.f);
    }
    __syncthreads();

    // v3: 1 output per row, 8 threads per row
    {
        int r = t >> 3, k8 = t & 7;
        float a = 0.f;
        #pragma unroll
        for (int kk = 0; kk < 32; kk += 4) {
            int k = k8 * 32 + kk;
            float4 hv = *(const float4*)&sm.ha[r * NH + k];
            a = fmaf(hv.x, vW3[k + 0], a);
            a = fmaf(hv.y, vW3[k + 1], a);
            a = fmaf(hv.z, vW3[k + 2], a);
            a = fmaf(hv.w, vW3[k + 3], a);
        }
        a += __shfl_down_sync(0xffffffffu, a, 4, 8);
        a += __shfl_down_sync(0xffffffffu, a, 2, 8);
        a += __shfl_down_sync(0xffffffffu, a, 1, 8);
        if (k8 == 0)
            out[(size_t)NB * NOUT + rb + r] = a + vb3[0];
    }
}

// ---------------------------------------------------------------------------
extern "C" void kernel_launch(void* const* d_in, const int* in_sizes, int n_in,
                              void* d_out, int out_size)
{
    const float* obs = (const float*)d_in[0];
    const float* sW1 = (const float*)d_in[1];
    const float* sb1 = (const float*)d_in[2];
    const float* sW2 = (const float*)d_in[3];
    const float* sb2 = (const float*)d_in[4];
    const float* sW3 = (const float*)d_in[5];
    const float* sb3 = (const float*)d_in[6];
    const float* aW1 = (const float*)d_in[7];
    const float* ab1 = (const float*)d_in[8];
    const float* aW2 = (const float*)d_in[9];
    const float* ab2 = (const float*)d_in[10];
    const float* aW3 = (const float*)d_in[11];
    const float* ab3 = (const float*)d_in[12];
    const float* vW1 = (const float*)d_in[13];
    const float* vb1 = (const float*)d_in[14];
    const float* vW2 = (const float*)d_in[15];
    const float* vb2 = (const float*)d_in[16];
    const float* vW3 = (const float*)d_in[17];
    const float* vb3 = (const float*)d_in[18];
    float* out = (float*)d_out;

    cudaFuncSetAttribute(embed_kernel, cudaFuncAttributeMaxDynamicSharedMemorySize,
                         (int)sizeof(SmemA));
    cudaFuncSetAttribute(heads_kernel, cudaFuncAttributeMaxDynamicSharedMemorySize,
                         (int)sizeof(SmemB));

    embed_kernel<<<NB, 256, sizeof(SmemA)>>>(obs, sW1, sb1, sW2, sb2, sW3, sb3);
    heads_kernel<<<NB / 32, 256, sizeof(SmemB)>>>(out, aW1, ab1, aW2, ab2, aW3, ab3,
                                                  vW1, vb1, vW2, vb2, vW3, vb3);
}

// round 7
// speedup vs baseline: 3.0759x; 3.0759x over previous
#include <cuda_runtime.h>
#include <cuda_bf16.h>
#include <cstdint>

#define NB    16384
#define NS    37
#define NF    17
#define NOWN  9
#define NH    256
#define NE    128
#define NCAT  137
#define NOUT  23

#define GBATCH 3
#define OBS_STRIDE ((NS + 1) * NF)

// ---------------------------------------------------------------------------
// device globals
// ---------------------------------------------------------------------------
__device__ float g_cat[(size_t)NB * NCAT];

// prepped weights: bf16 hi/lo split, B layout [N rows][K cols], chunked by K.
// gW1: 1 chunk [256][32]; gW2: 4 chunks [256][64]; gW3: 4 chunks [128][64]
__device__ __align__(16) __nv_bfloat16 gW1h[256 * 32],     gW1l[256 * 32];
__device__ __align__(16) __nv_bfloat16 gW2h[4 * 256 * 64], gW2l[4 * 256 * 64];
__device__ __align__(16) __nv_bfloat16 gW3h[4 * 128 * 64], gW3l[4 * 128 * 64];

// ---------------------------------------------------------------------------
// smem layout (bytes). A rows stride 528 (16 mod 128 -> conflict-free LDSM),
// B rows stride 144 (16 mod 128 -> conflict-free LDSM).
// ---------------------------------------------------------------------------
#define SM_BIAS  0
#define SM_MASK  1024
#define SM_AH    2048
#define SM_AL    (SM_AH + 67584)        // 128 * 528
#define SM_BH    (SM_AL + 67584)
#define SM_BL    (SM_BH + 36864)        // 256 * 144
#define SM_RED   SM_BH                  // alias: 128 rows x 528B fp32 reduce buf
#define SM_TOTAL (SM_BL + 36864)        // 210944 bytes

// ---------------------------------------------------------------------------
// helpers
// ---------------------------------------------------------------------------
__device__ __forceinline__ uint32_t smem_u32(const void* p) {
    uint32_t a;
    asm("{ .reg .u64 t; cvta.to.shared.u64 t, %1; cvt.u32.u64 %0, t; }"
        : "=r"(a) : "l"(p));
    return a;
}

__device__ __forceinline__ void mma16816(float* d, const uint32_t* a, const uint32_t* b) {
    asm volatile(
        "mma.sync.aligned.m16n8k16.row.col.f32.bf16.bf16.f32 "
        "{%0,%1,%2,%3}, {%4,%5,%6,%7}, {%8,%9}, {%0,%1,%2,%3};"
        : "+f"(d[0]), "+f"(d[1]), "+f"(d[2]), "+f"(d[3])
        : "r"(a[0]), "r"(a[1]), "r"(a[2]), "r"(a[3]), "r"(b[0]), "r"(b[1]));
}

__device__ __forceinline__ void ldsm4(uint32_t* r, uint32_t addr) {
    asm volatile("ldmatrix.sync.aligned.m8n8.x4.shared.b16 {%0,%1,%2,%3}, [%4];"
        : "=r"(r[0]), "=r"(r[1]), "=r"(r[2]), "=r"(r[3]) : "r"(addr));
}

__device__ __forceinline__ void split2(float v0, float v1, uint32_t& h, uint32_t& l) {
    __nv_bfloat162 hh, ll;
    hh.x = __float2bfloat16(v0);
    hh.y = __float2bfloat16(v1);
    ll.x = __float2bfloat16(v0 - __bfloat162float(hh.x));
    ll.y = __float2bfloat16(v1 - __bfloat162float(hh.y));
    h = *(uint32_t*)&hh;
    l = *(uint32_t*)&ll;
}

// ---------------------------------------------------------------------------
// prep: fp32 weights -> bf16 hi/lo, transposed to [N][K] chunk tiles
// ---------------------------------------------------------------------------
__global__ void prep_kernel(const float* __restrict__ sW1,
                            const float* __restrict__ sW2,
                            const float* __restrict__ sW3) {
    int idx = blockIdx.x * 256 + threadIdx.x;
    float x0, x1;
    char *dh, *dl;
    uint32_t off;
    if (idx < 4096) {                          // W1: [256][32], pairs
        int n = idx >> 4, k = (idx & 15) * 2;
        x0 = (k     < NF) ? sW1[k * NH + n]       : 0.f;
        x1 = (k + 1 < NF) ? sW1[(k + 1) * NH + n] : 0.f;
        off = (uint32_t)(n * 64 + k * 2);
        dh = (char*)gW1h; dl = (char*)gW1l;
    } else if (idx < 4096 + 32768) {           // W2: 4 chunks [256][64]
        int i = idx - 4096;
        int c = i >> 13, rem = i & 8191;
        int n = rem >> 5, k = (rem & 31) * 2;
        x0 = sW2[(c * 64 + k) * NH + n];
        x1 = sW2[(c * 64 + k + 1) * NH + n];
        off = (uint32_t)(c * 32768 + n * 128 + k * 2);
        dh = (char*)gW2h; dl = (char*)gW2l;
    } else if (idx < 4096 + 32768 + 16384) {   // W3: 4 chunks [128][64]
        int i = idx - 36864;
        int c = i >> 12, rem = i & 4095;
        int n = rem >> 5, k = (rem & 31) * 2;
        x0 = sW3[(c * 64 + k) * NE + n];
        x1 = sW3[(c * 64 + k + 1) * NE + n];
        off = (uint32_t)(c * 16384 + n * 128 + k * 2);
        dh = (char*)gW3h; dl = (char*)gW3l;
    } else {
        return;
    }
    __nv_bfloat162 h, l;
    h.x = __float2bfloat16(x0);
    h.y = __float2bfloat16(x1);
    l.x = __float2bfloat16(x0 - __bfloat162float(h.x));
    l.y = __float2bfloat16(x1 - __bfloat162float(h.y));
    *(__nv_bfloat162*)(dh + off) = h;
    *(__nv_bfloat162*)(dl + off) = l;
}

// ---------------------------------------------------------------------------
// one layer: C[128,Nn] += A[128,Kp] * W[Kp,Nn], split-bf16 x3 via mma.sync
// A in smem (hi/lo), B chunks staged from global. acc: [Nn/8][4] fp32 frags.
// ---------------------------------------------------------------------------
template<int Nn, int Kp>
__device__ __forceinline__ void layer_mma(
    char* sm, uint32_t smu, int tid,
    const __nv_bfloat16* __restrict__ gwh,
    const __nv_bfloat16* __restrict__ gwl,
    const float* __restrict__ bias,
    float (*acc)[4])
{
    constexpr int KCH = (Kp < 64) ? Kp : 64;
    constexpr int F4R = KCH / 8;               // float4s per B row
    const int lane = tid & 31;
    const int w = tid >> 5;
    const int j = lane >> 3, wi = lane & 7;
    // A ldsm x4: matrices (m,k): j0=(m0,k0) j1=(m8,k0) j2=(m0,k8) j3=(m8,k8)
    const uint32_t aaddr = smu + SM_AH +
        (uint32_t)((16 * w + (j & 1) * 8 + wi) * 528 + ((j >> 1) * 8) * 2);
    // B ldsm x4: matrices (n,k): j0=(n0,k0) j1=(n0,k8) j2=(n8,k0) j3=(n8,k8)
    const uint32_t baddr0 = smu + SM_BH +
        (uint32_t)(((j >> 1) * 8 + wi) * 144 + ((j & 1) * 8) * 2);

    float* sb = (float*)(sm + SM_BIAS);
    for (int i = tid; i < Nn; i += 256) sb[i] = bias[i];

    #pragma unroll 1
    for (int kc = 0; kc < Kp; kc += KCH) {
        const float4* srch = (const float4*)gwh + (kc / KCH) * (Nn * F4R);
        const float4* srcl = (const float4*)gwl + (kc / KCH) * (Nn * F4R);
        for (int i = tid; i < Nn * F4R; i += 256) {
            int row = i / F4R, q = i - row * F4R;
            *(float4*)(sm + SM_BH + row * 144 + q * 16) = srch[i];
            *(float4*)(sm + SM_BL + row * 144 + q * 16) = srcl[i];
        }
        __syncthreads();
        #pragma unroll
        for (int ks = 0; ks < KCH / 16; ks++) {
            uint32_t ah[4], al[4];
            ldsm4(ah, aaddr + (uint32_t)((kc + ks * 16) * 2));
            ldsm4(al, aaddr + (uint32_t)((kc + ks * 16) * 2) + (SM_AL - SM_AH));
            #pragma unroll
            for (int g = 0; g < Nn / 16; g++) {
                uint32_t bh[4], bl[4];
                uint32_t ba = baddr0 + (uint32_t)(g * (16 * 144) + ks * 32);
                ldsm4(bh, ba);
                ldsm4(bl, ba + (SM_BL - SM_BH));
                mma16816(acc[2 * g],     ah, bh);
                mma16816(acc[2 * g + 1], ah, bh + 2);
                mma16816(acc[2 * g],     ah, bl);
                mma16816(acc[2 * g + 1], ah, bl + 2);
                mma16816(acc[2 * g],     al, bh);
                mma16816(acc[2 * g + 1], al, bh + 2);
            }
        }
        __syncthreads();
    }
}

// epilogue: relu(acc + bias) -> split bf16 hi/lo into A tiles (in place safe)
template<int Nn>
__device__ __forceinline__ void epi_store(char* sm, int tid, float (*acc)[4])
{
    const int lane = tid & 31, w = tid >> 5;
    const int r0 = 16 * w + (lane >> 2);
    const float* sb = (const float*)(sm + SM_BIAS);
    #pragma unroll
    for (int f = 0; f < Nn / 8; f++) {
        int c = 8 * f + 2 * (lane & 3);
        float b0 = sb[c], b1 = sb[c + 1];
        uint32_t h, l;
        split2(fmaxf(acc[f][0] + b0, 0.f), fmaxf(acc[f][1] + b1, 0.f), h, l);
        *(uint32_t*)(sm + SM_AH + r0 * 528 + c * 2) = h;
        *(uint32_t*)(sm + SM_AL + r0 * 528 + c * 2) = l;
        split2(fmaxf(acc[f][2] + b0, 0.f), fmaxf(acc[f][3] + b1, 0.f), h, l);
        *(uint32_t*)(sm + SM_AH + (r0 + 8) * 528 + c * 2) = h;
        *(uint32_t*)(sm + SM_AL + (r0 + 8) * 528 + c * 2) = l;
    }
    __syncthreads();
}

// final epilogue: mask * relu(acc + bias) -> smem, masked segment sum -> g_cat
__device__ __forceinline__ void epi_final(char* sm, int tid, float (*acc)[4],
                                          int b0batch, int nb)
{
    const int lane = tid & 31, w = tid >> 5;
    const int r0 = 16 * w + (lane >> 2);
    const float* sb = (const float*)(sm + SM_BIAS);
    const float* mk = (const float*)(sm + SM_MASK);
    const float m0 = mk[r0], m1 = mk[r0 + 8];
    #pragma unroll
    for (int f = 0; f < 16; f++) {
        int c = 8 * f + 2 * (lane & 3);
        float b0 = sb[c], b1 = sb[c + 1];
        float2 v;
        v.x = m0 * fmaxf(acc[f][0] + b0, 0.f);
        v.y = m0 * fmaxf(acc[f][1] + b1, 0.f);
        *(float2*)(sm + SM_RED + r0 * 528 + c * 4) = v;
        v.x = m1 * fmaxf(acc[f][2] + b0, 0.f);
        v.y = m1 * fmaxf(acc[f][3] + b1, 0.f);
        *(float2*)(sm + SM_RED + (r0 + 8) * 528 + c * 4) = v;
    }
    __syncthreads();
    const float* red = (const float*)(sm + SM_RED);
    for (int p = tid; p < 3 * 128; p += 256) {
        int bg = p >> 7, c = p & 127;
        if (bg < nb) {
            float s = 0.f;
            #pragma unroll
            for (int i = 0; i < NS; i++)
                s += red[(bg * 37 + i) * 132 + c];
            g_cat[(size_t)(b0batch + bg) * NCAT + c] = s;
        }
    }
}

// ---------------------------------------------------------------------------
// embed: token MLP 17->256->256->128 via mma.sync, masked segment sum
// ---------------------------------------------------------------------------
__global__ __launch_bounds__(256, 1) void embed_mma_kernel(
    const float* __restrict__ obs,
    const float* __restrict__ sb1, const float* __restrict__ sb2,
    const float* __restrict__ sb3)
{
    extern __shared__ char sm[];
    const uint32_t smu = smem_u32(sm);
    const int tid = threadIdx.x;
    const int b0 = blockIdx.x * GBATCH;
    const int nb = (NB - b0 < GBATCH) ? (NB - b0) : GBATCH;

    // ---- input phase: X rows (K pad to 32) -> A hi/lo; mask; s_own -> g_cat
    float* maskv = (float*)(sm + SM_MASK);
    if (tid < 128) {
        const int row = tid;
        const int g = row / 37, s = row - g * 37;
        const bool valid = (row < 111) && (g < nb);
        float x[32];
        #pragma unroll
        for (int f = 0; f < 32; f++) x[f] = 0.f;
        float sabs = 0.f;
        if (valid) {
            const float* p = obs + (size_t)(b0 + g) * OBS_STRIDE + (size_t)(s + 1) * NF;
            #pragma unroll
            for (int f = 0; f < NF; f++) { x[f] = p[f]; sabs += fabsf(x[f]); }
        }
        maskv[row] = (valid && sabs != 0.f) ? 1.f : 0.f;
        #pragma unroll
        for (int c = 0; c < 32; c += 2) {
            uint32_t h, l;
            split2(x[c], x[c + 1], h, l);
            *(uint32_t*)(sm + SM_AH + row * 528 + c * 2) = h;
            *(uint32_t*)(sm + SM_AL + row * 528 + c * 2) = l;
        }
    } else if (tid < 128 + 27) {
        int q = tid - 128, g = q / 9, jj = q - 9 * g;
        if (g < nb)
            g_cat[(size_t)(b0 + g) * NCAT + NE + jj] =
                obs[(size_t)(b0 + g) * OBS_STRIDE + jj];
    }
    __syncthreads();

    // ---- L1: 32(pad of 17) -> 256
    {
        float acc[32][4];
        #pragma unroll
        for (int f = 0; f < 32; f++)
            acc[f][0] = acc[f][1] = acc[f][2] = acc[f][3] = 0.f;
        layer_mma<256, 32>(sm, smu, tid, gW1h, gW1l, sb1, acc);
        epi_store<256>(sm, tid, acc);
    }
    // ---- L2: 256 -> 256
    {
        float acc[32][4];
        #pragma unroll
        for (int f = 0; f < 32; f++)
            acc[f][0] = acc[f][1] = acc[f][2] = acc[f][3] = 0.f;
        layer_mma<256, 256>(sm, smu, tid, gW2h, gW2l, sb2, acc);
        epi_store<256>(sm, tid, acc);
    }
    // ---- L3: 256 -> 128, masked segment sum
    {
        float acc[16][4];
        #pragma unroll
        for (int f = 0; f < 16; f++)
            acc[f][0] = acc[f][1] = acc[f][2] = acc[f][3] = 0.f;
        layer_mma<128, 256>(sm, smu, tid, gW3h, gW3l, sb3, acc);
        epi_final(sm, tid, acc, b0, nb);
    }
}

// ---------------------------------------------------------------------------
// Kernel B: action/value heads, 32 batch rows per CTA (unchanged, passing)
// ---------------------------------------------------------------------------
struct SmemB {
    float cats[32 * 160];
    float ha[32 * NH];
    float wT[NH * 36];
};

__global__ __launch_bounds__(256, 2) void heads_kernel(
    float* __restrict__ out,
    const float* __restrict__ aW1, const float* __restrict__ ab1,
    const float* __restrict__ aW2, const float* __restrict__ ab2,
    const float* __restrict__ aW3, const float* __restrict__ ab3,
    const float* __restrict__ vW1, const float* __restrict__ vb1,
    const float* __restrict__ vW2, const float* __restrict__ vb2,
    const float* __restrict__ vW3, const float* __restrict__ vb3)
{
    extern __shared__ char smraw[];
    SmemB& sm = *reinterpret_cast<SmemB*>(smraw);
    const int t  = threadIdx.x;
    const int rb = blockIdx.x * 32;

    for (int idx = t; idx < 32 * 160; idx += 256) {
        int r = idx / 160, c = idx % 160;
        sm.cats[idx] = (c < NCAT) ? g_cat[(size_t)(rb + r) * NCAT + c] : 0.f;
    }

    float acc[32];

    // ========== branch a ==========
    #pragma unroll
    for (int r = 0; r < 32; r++) acc[r] = 0.f;
    #pragma unroll 1
    for (int kc = 0; kc < 160; kc += 32) {
        __syncthreads();
        for (int idx = t; idx < 32 * NH; idx += 256) {
            int kk = idx >> 8, j = idx & 255;
            int k = kc + kk;
            sm.wT[j * 36 + kk] = (k < NCAT) ? aW1[k * NH + j] : 0.f;
        }
        __syncthreads();
        #pragma unroll
        for (int kk = 0; kk < 32; kk += 4) {
            float4 w = *(const float4*)&sm.wT[t * 36 + kk];
            #pragma unroll
            for (int r = 0; r < 32; r++) {
                float4 cv = *(const float4*)&sm.cats[r * 160 + kc + kk];
                acc[r] = fmaf(cv.x, w.x, acc[r]);
                acc[r] = fmaf(cv.y, w.y, acc[r]);
                acc[r] = fmaf(cv.z, w.z, acc[r]);
                acc[r] = fmaf(cv.w, w.w, acc[r]);
            }
        }
    }
    __syncthreads();
    {
        const float bb = ab1[t];
        #pragma unroll 1
        for (int r = 0; r < 32; r++) sm.ha[r * NH + t] = fmaxf(acc[r] + bb, 0.f);
    }

    #pragma unroll
    for (int r = 0; r < 32; r++) acc[r] = 0.f;
    #pragma unroll 1
    for (int kc = 0; kc < NH; kc += 32) {
        __syncthreads();
        for (int idx = t; idx < 32 * NH; idx += 256) {
            int kk = idx >> 8, j = idx & 255;
            sm.wT[j * 36 + kk] = aW2[(kc + kk) * NH + j];
        }
        __syncthreads();
        #pragma unroll
        for (int kk = 0; kk < 32; kk += 4) {
            float4 w = *(const float4*)&sm.wT[t * 36 + kk];
            #pragma unroll
            for (int r = 0; r < 32; r++) {
                float4 hv = *(const float4*)&sm.ha[r * NH + kc + kk];
                acc[r] = fmaf(hv.x, w.x, acc[r]);
                acc[r] = fmaf(hv.y, w.y, acc[r]);
                acc[r] = fmaf(hv.z, w.z, acc[r]);
                acc[r] = fmaf(hv.w, w.w, acc[r]);
            }
        }
    }
    __syncthreads();
    {
        const float bb = ab2[t];
        #pragma unroll 1
        for (int r = 0; r < 32; r++) sm.ha[r * NH + t] = fmaxf(acc[r] + bb, 0.f);
    }
    __syncthreads();

    for (int idx = t; idx < 32 * NOUT; idx += 256) {
        int r = idx / NOUT, c = idx - r * NOUT;
        float a = ab3[c];
        #pragma unroll 4
        for (int k = 0; k < NH; k += 4) {
            float4 hv = *(const float4*)&sm.ha[r * NH + k];
            a = fmaf(hv.x, aW3[(k + 0) * NOUT + c], a);
            a = fmaf(hv.y, aW3[(k + 1) * NOUT + c], a);
            a = fmaf(hv.z, aW3[(k + 2) * NOUT + c], a);
            a = fmaf(hv.w, aW3[(k + 3) * NOUT + c], a);
        }
        out[(size_t)(rb + r) * NOUT + c] = a;
    }
    __syncthreads();

    // ========== branch v ==========
    #pragma unroll
    for (int r = 0; r < 32; r++) acc[r] = 0.f;
    #pragma unroll 1
    for (int kc = 0; kc < 160; kc += 32) {
        __syncthreads();
        for (int idx = t; idx < 32 * NH; idx += 256) {
            int kk = idx >> 8, j = idx & 255;
            int k = kc + kk;
            sm.wT[j * 36 + kk] = (k < NCAT) ? vW1[k * NH + j] : 0.f;
        }
        __syncthreads();
        #pragma unroll
        for (int kk = 0; kk < 32; kk += 4) {
            float4 w = *(const float4*)&sm.wT[t * 36 + kk];
            #pragma unroll
            for (int r = 0; r < 32; r++) {
                float4 cv = *(const float4*)&sm.cats[r * 160 + kc + kk];
                acc[r] = fmaf(cv.x, w.x, acc[r]);
                acc[r] = fmaf(cv.y, w.y, acc[r]);
                acc[r] = fmaf(cv.z, w.z, acc[r]);
                acc[r] = fmaf(cv.w, w.w, acc[r]);
            }
        }
    }
    __syncthreads();
    {
        const float bb = vb1[t];
        #pragma unroll 1
        for (int r = 0; r < 32; r++) sm.ha[r * NH + t] = fmaxf(acc[r] + bb, 0.f);
    }

    #pragma unroll
    for (int r = 0; r < 32; r++) acc[r] = 0.f;
    #pragma unroll 1
    for (int kc = 0; kc < NH; kc += 32) {
        __syncthreads();
        for (int idx = t; idx < 32 * NH; idx += 256) {
            int kk = idx >> 8, j = idx & 255;
            sm.wT[j * 36 + kk] = vW2[(kc + kk) * NH + j];
        }
        __syncthreads();
        #pragma unroll
        for (int kk = 0; kk < 32; kk += 4) {
            float4 w = *(const float4*)&sm.wT[t * 36 + kk];
            #pragma unroll
            for (int r = 0; r < 32; r++) {
                float4 hv = *(const float4*)&sm.ha[r * NH + kc + kk];
                acc[r] = fmaf(hv.x, w.x, acc[r]);
                acc[r] = fmaf(hv.y, w.y, acc[r]);
                acc[r] = fmaf(hv.z, w.z, acc[r]);
                acc[r] = fmaf(hv.w, w.w, acc[r]);
            }
        }
    }
    __syncthreads();
    {
        const float bb = vb2[t];
        #pragma unroll 1
        for (int r = 0; r < 32; r++) sm.ha[r * NH + t] = fmaxf(acc[r] + bb, 0.f);
    }
    __syncthreads();

    {
        int r = t >> 3, k8 = t & 7;
        float a = 0.f;
        #pragma unroll
        for (int kk = 0; kk < 32; kk += 4) {
            int k = k8 * 32 + kk;
            float4 hv = *(const float4*)&sm.ha[r * NH + k];
            a = fmaf(hv.x, vW3[k + 0], a);
            a = fmaf(hv.y, vW3[k + 1], a);
            a = fmaf(hv.z, vW3[k + 2], a);
            a = fmaf(hv.w, vW3[k + 3], a);
        }
        a += __shfl_down_sync(0xffffffffu, a, 4, 8);
        a += __shfl_down_sync(0xffffffffu, a, 2, 8);
        a += __shfl_down_sync(0xffffffffu, a, 1, 8);
        if (k8 == 0)
            out[(size_t)NB * NOUT + rb + r] = a + vb3[0];
    }
}

// ---------------------------------------------------------------------------
extern "C" void kernel_launch(void* const* d_in, const int* in_sizes, int n_in,
                              void* d_out, int out_size)
{
    const float* obs = (const float*)d_in[0];
    const float* sW1 = (const float*)d_in[1];
    const float* sb1 = (const float*)d_in[2];
    const float* sW2 = (const float*)d_in[3];
    const float* sb2 = (const float*)d_in[4];
    const float* sW3 = (const float*)d_in[5];
    const float* sb3 = (const float*)d_in[6];
    const float* aW1 = (const float*)d_in[7];
    const float* ab1 = (const float*)d_in[8];
    const float* aW2 = (const float*)d_in[9];
    const float* ab2 = (const float*)d_in[10];
    const float* aW3 = (const float*)d_in[11];
    const float* ab3 = (const float*)d_in[12];
    const float* vW1 = (const float*)d_in[13];
    const float* vb1 = (const float*)d_in[14];
    const float* vW2 = (const float*)d_in[15];
    const float* vb2 = (const float*)d_in[16];
    const float* vW3 = (const float*)d_in[17];
    const float* vb3 = (const float*)d_in[18];
    float* out = (float*)d_out;

    cudaFuncSetAttribute(embed_mma_kernel, cudaFuncAttributeMaxDynamicSharedMemorySize,
                         SM_TOTAL);
    cudaFuncSetAttribute(heads_kernel, cudaFuncAttributeMaxDynamicSharedMemorySize,
                         (int)sizeof(SmemB));

    prep_kernel<<<208, 256>>>(sW1, sW2, sW3);
    embed_mma_kernel<<<(NB + GBATCH - 1) / GBATCH, 256, SM_TOTAL>>>(obs, sb1, sb2, sb3);
    heads_kernel<<<NB / 32, 256, sizeof(SmemB)>>>(out, aW1, ab1, aW2, ab2, aW3, ab3,
                                                  vW1, vb1, vW2, vb2, vW3, vb3);
}

// round 8
// speedup vs baseline: 4.0154x; 1.3055x over previous
#include <cuda_runtime.h>
#include <cuda_bf16.h>
#include <cstdint>

#define NB    16384
#define NS    37
#define NF    17
#define NOWN  9
#define NH    256
#define NE    128
#define NCAT  137
#define NOUT  23

#define GBATCH 3
#define OBS_STRIDE ((NS + 1) * NF)

// ---------------------------------------------------------------------------
// device globals
// ---------------------------------------------------------------------------
__device__ float g_cat[(size_t)NB * NCAT];

// prepped weights, bf16 hi/lo split, B layout [chunk][N rows][32 k] (64B rows)
__device__ __align__(16) __nv_bfloat16 gW1h[1 * 256 * 32], gW1l[1 * 256 * 32];
__device__ __align__(16) __nv_bfloat16 gW2h[8 * 256 * 32], gW2l[8 * 256 * 32];
__device__ __align__(16) __nv_bfloat16 gW3h[8 * 128 * 32], gW3l[8 * 128 * 32];
__device__ __align__(16) __nv_bfloat16 hA1h[5 * 256 * 32], hA1l[5 * 256 * 32];
__device__ __align__(16) __nv_bfloat16 hA2h[8 * 256 * 32], hA2l[8 * 256 * 32];
__device__ __align__(16) __nv_bfloat16 hA3h[8 * 32 * 32],  hA3l[8 * 32 * 32];
__device__ __align__(16) __nv_bfloat16 hV1h[5 * 256 * 32], hV1l[5 * 256 * 32];
__device__ __align__(16) __nv_bfloat16 hV2h[8 * 256 * 32], hV2l[8 * 256 * 32];

// ---------------------------------------------------------------------------
// smem layout (bytes). A rows stride 528; B rows stride 80. Both give the 8
// ldmatrix row addresses distinct 16B slots mod 128 -> conflict-free LDSM.
// ---------------------------------------------------------------------------
#define SM_BIAS  0
#define SM_MASK  1024
#define SM_AH    2048
#define ALOFF    67584                   // 128 * 528
#define SM_AL    (SM_AH + ALOFF)
#define SM_B0    (SM_AL + ALOFF)         // 137216
#define BSTG     40960                   // one stage: 256 rows * 80B * 2 parts
#define SM_RED   SM_B0                   // alias over B stages
#define SM_TOTAL (SM_B0 + 2 * BSTG)      // 219136

// ---------------------------------------------------------------------------
// helpers
// ---------------------------------------------------------------------------
__device__ __forceinline__ uint32_t smem_u32(const void* p) {
    uint32_t a;
    asm("{ .reg .u64 t; cvta.to.shared.u64 t, %1; cvt.u32.u64 %0, t; }"
        : "=r"(a) : "l"(p));
    return a;
}

__device__ __forceinline__ void mma16816(float* d, const uint32_t* a, const uint32_t* b) {
    asm volatile(
        "mma.sync.aligned.m16n8k16.row.col.f32.bf16.bf16.f32 "
        "{%0,%1,%2,%3}, {%4,%5,%6,%7}, {%8,%9}, {%0,%1,%2,%3};"
        : "+f"(d[0]), "+f"(d[1]), "+f"(d[2]), "+f"(d[3])
        : "r"(a[0]), "r"(a[1]), "r"(a[2]), "r"(a[3]), "r"(b[0]), "r"(b[1]));
}

__device__ __forceinline__ void ldsm4(uint32_t* r, uint32_t addr) {
    asm volatile("ldmatrix.sync.aligned.m8n8.x4.shared.b16 {%0,%1,%2,%3}, [%4];"
        : "=r"(r[0]), "=r"(r[1]), "=r"(r[2]), "=r"(r[3]) : "r"(addr));
}

__device__ __forceinline__ void split2(float v0, float v1, uint32_t& h, uint32_t& l) {
    __nv_bfloat162 hh, ll;
    hh.x = __float2bfloat16(v0);
    hh.y = __float2bfloat16(v1);
    ll.x = __float2bfloat16(v0 - __bfloat162float(hh.x));
    ll.y = __float2bfloat16(v1 - __bfloat162float(hh.y));
    h = *(uint32_t*)&hh;
    l = *(uint32_t*)&ll;
}

#define CP16(d, s) \
    asm volatile("cp.async.cg.shared.global [%0], [%1], 16;" \
                 :: "r"(d), "l"(s) : "memory")
#define CP_COMMIT() asm volatile("cp.async.commit_group;" ::: "memory")
#define CP_WAIT(n)  asm volatile("cp.async.wait_group %0;" :: "n"(n) : "memory")

// ---------------------------------------------------------------------------
// prep: fp32 [K][N] weights -> bf16 hi/lo [chunk][Npad][32] tiles (K pad, N pad)
// ---------------------------------------------------------------------------
__global__ void prep_w(const float* __restrict__ src, int sel,
                       int Nn, int Npad, int Kk, int Kpad)
{
    __nv_bfloat16 *dh, *dl;
    switch (sel) {
        case 0: dh = gW1h; dl = gW1l; break;
        case 1: dh = gW2h; dl = gW2l; break;
        case 2: dh = gW3h; dl = gW3l; break;
        case 3: dh = hA1h; dl = hA1l; break;
        case 4: dh = hA2h; dl = hA2l; break;
        case 5: dh = hA3h; dl = hA3l; break;
        case 6: dh = hV1h; dl = hV1l; break;
        default: dh = hV2h; dl = hV2l; break;
    }
    int idx = blockIdx.x * 256 + threadIdx.x;
    int kh = Kpad >> 1;
    if (idx >= Npad * kh) return;
    int n = idx / kh, k = (idx - n * kh) * 2;
    float x0 = (n < Nn && k     < Kk) ? src[k * Nn + n]       : 0.f;
    float x1 = (n < Nn && k + 1 < Kk) ? src[(k + 1) * Nn + n] : 0.f;
    int ch = k >> 5, kk = k & 31;
    size_t off = (size_t)ch * Npad * 32 + n * 32 + kk;
    __nv_bfloat162 h, l;
    h.x = __float2bfloat16(x0);
    h.y = __float2bfloat16(x1);
    l.x = __float2bfloat16(x0 - __bfloat162float(h.x));
    l.y = __float2bfloat16(x1 - __bfloat162float(h.y));
    *(__nv_bfloat162*)(dh + off) = h;
    *(__nv_bfloat162*)(dl + off) = l;
}

// ---------------------------------------------------------------------------
// one layer: C[128,Nn] += A[128,Kp]*W, split-bf16 x3, cp.async double-buffered
// ---------------------------------------------------------------------------
template<int Nn, int Kp>
__device__ __forceinline__ void layer_mma(
    char* sm, uint32_t smu, int tid,
    const __nv_bfloat16* __restrict__ gwh,
    const __nv_bfloat16* __restrict__ gwl,
    const float* __restrict__ bias, int nbias,
    float (*acc)[4])
{
    constexpr int NCH = Kp / 32;
    const int lane = tid & 31;
    const int w = tid >> 5;
    const int j = lane >> 3, wi = lane & 7;
    const uint32_t aaddr = smu + SM_AH +
        (uint32_t)((16 * w + (j & 1) * 8 + wi) * 528 + ((j >> 1) * 8) * 2);
    const uint32_t bfrag = (uint32_t)(((j >> 1) * 8 + wi) * 80 + (j & 1) * 16);

    float* sb = (float*)(sm + SM_BIAS);
    for (int i = tid; i < nbias; i += 256) sb[i] = bias[i];

    // preload chunk 0 -> stage 0
    {
        const char* gh = (const char*)gwh;
        const char* gl = (const char*)gwl;
        uint32_t st = smu + SM_B0;
        for (int i = tid; i < Nn * 4; i += 256) {
            uint32_t d = (uint32_t)((i >> 2) * 80 + (i & 3) * 16);
            CP16(st + d, gh + i * 16);
            CP16(st + (uint32_t)(Nn * 80) + d, gl + i * 16);
        }
        CP_COMMIT();
    }

    #pragma unroll 1
    for (int kc = 0; kc < NCH; kc++) {
        if (kc + 1 < NCH) {
            const char* gh = (const char*)(gwh + (size_t)(kc + 1) * Nn * 32);
            const char* gl = (const char*)(gwl + (size_t)(kc + 1) * Nn * 32);
            uint32_t st = smu + SM_B0 + (uint32_t)(((kc + 1) & 1) * BSTG);
            for (int i = tid; i < Nn * 4; i += 256) {
                uint32_t d = (uint32_t)((i >> 2) * 80 + (i & 3) * 16);
                CP16(st + d, gh + i * 16);
                CP16(st + (uint32_t)(Nn * 80) + d, gl + i * 16);
            }
            CP_COMMIT();
            CP_WAIT(1);
        } else {
            CP_WAIT(0);
        }
        __syncthreads();

        const uint32_t bbase = smu + SM_B0 + (uint32_t)((kc & 1) * BSTG) + bfrag;
        #pragma unroll
        for (int ks = 0; ks < 2; ks++) {
            uint32_t ah[4], al[4];
            uint32_t ao = aaddr + (uint32_t)((kc * 32 + ks * 16) * 2);
            ldsm4(ah, ao);
            ldsm4(al, ao + ALOFF);
            #pragma unroll
            for (int g = 0; g < Nn / 16; g++) {
                uint32_t bh[4], bl[4];
                uint32_t ba = bbase + (uint32_t)(g * 1280 + ks * 32);
                ldsm4(bh, ba);
                ldsm4(bl, ba + (uint32_t)(Nn * 80));
                mma16816(acc[2 * g],     ah, bh);
                mma16816(acc[2 * g + 1], ah, bh + 2);
                mma16816(acc[2 * g],     ah, bl);
                mma16816(acc[2 * g + 1], ah, bl + 2);
                mma16816(acc[2 * g],     al, bh);
                mma16816(acc[2 * g + 1], al, bh + 2);
            }
        }
        __syncthreads();
    }
}

// epilogue: relu(acc + bias) -> split bf16 hi/lo into A tiles
template<int Nn>
__device__ __forceinline__ void epi_store(char* sm, int tid, float (*acc)[4])
{
    const int lane = tid & 31, w = tid >> 5;
    const int r0 = 16 * w + (lane >> 2);
    const float* sb = (const float*)(sm + SM_BIAS);
    #pragma unroll
    for (int f = 0; f < Nn / 8; f++) {
        int c = 8 * f + 2 * (lane & 3);
        float b0 = sb[c], b1 = sb[c + 1];
        uint32_t h, l;
        split2(fmaxf(acc[f][0] + b0, 0.f), fmaxf(acc[f][1] + b1, 0.f), h, l);
        *(uint32_t*)(sm + SM_AH + r0 * 528 + c * 2) = h;
        *(uint32_t*)(sm + SM_AL + r0 * 528 + c * 2) = l;
        split2(fmaxf(acc[f][2] + b0, 0.f), fmaxf(acc[f][3] + b1, 0.f), h, l);
        *(uint32_t*)(sm + SM_AH + (r0 + 8) * 528 + c * 2) = h;
        *(uint32_t*)(sm + SM_AL + (r0 + 8) * 528 + c * 2) = l;
    }
    __syncthreads();
}

// embed final epilogue: mask * relu(acc + bias), masked segment sum -> g_cat
__device__ __forceinline__ void epi_final(char* sm, int tid, float (*acc)[4],
                                          int b0batch, int nb)
{
    const int lane = tid & 31, w = tid >> 5;
    const int r0 = 16 * w + (lane >> 2);
    const float* sb = (const float*)(sm + SM_BIAS);
    const float* mk = (const float*)(sm + SM_MASK);
    const float m0 = mk[r0], m1 = mk[r0 + 8];
    #pragma unroll
    for (int f = 0; f < 16; f++) {
        int c = 8 * f + 2 * (lane & 3);
        float b0 = sb[c], b1 = sb[c + 1];
        float2 v;
        v.x = m0 * fmaxf(acc[f][0] + b0, 0.f);
        v.y = m0 * fmaxf(acc[f][1] + b1, 0.f);
        *(float2*)(sm + SM_RED + r0 * 528 + c * 4) = v;
        v.x = m1 * fmaxf(acc[f][2] + b0, 0.f);
        v.y = m1 * fmaxf(acc[f][3] + b1, 0.f);
        *(float2*)(sm + SM_RED + (r0 + 8) * 528 + c * 4) = v;
    }
    __syncthreads();
    const float* red = (const float*)(sm + SM_RED);
    for (int p = tid; p < 3 * 128; p += 256) {
        int bg = p >> 7, c = p & 127;
        if (bg < nb) {
            float s = 0.f;
            #pragma unroll
            for (int i = 0; i < NS; i++)
                s += red[(bg * 37 + i) * 132 + c];
            g_cat[(size_t)(b0batch + bg) * NCAT + c] = s;
        }
    }
}

// ---------------------------------------------------------------------------
// embed: token MLP 17->256->256->128 via mma.sync, masked segment sum
// ---------------------------------------------------------------------------
__global__ __launch_bounds__(256, 1) void embed_mma_kernel(
    const float* __restrict__ obs,
    const float* __restrict__ sb1, const float* __restrict__ sb2,
    const float* __restrict__ sb3)
{
    extern __shared__ char sm[];
    const uint32_t smu = smem_u32(sm);
    const int tid = threadIdx.x;
    const int b0 = blockIdx.x * GBATCH;
    const int nb = (NB - b0 < GBATCH) ? (NB - b0) : GBATCH;

    float* maskv = (float*)(sm + SM_MASK);
    if (tid < 128) {
        const int row = tid;
        const int g = row / 37, s = row - g * 37;
        const bool valid = (row < 111) && (g < nb);
        float x[32];
        #pragma unroll
        for (int f = 0; f < 32; f++) x[f] = 0.f;
        float sabs = 0.f;
        if (valid) {
            const float* p = obs + (size_t)(b0 + g) * OBS_STRIDE + (size_t)(s + 1) * NF;
            #pragma unroll
            for (int f = 0; f < NF; f++) { x[f] = p[f]; sabs += fabsf(x[f]); }
        }
        maskv[row] = (valid && sabs != 0.f) ? 1.f : 0.f;
        #pragma unroll
        for (int c = 0; c < 32; c += 2) {
            uint32_t h, l;
            split2(x[c], x[c + 1], h, l);
            *(uint32_t*)(sm + SM_AH + row * 528 + c * 2) = h;
            *(uint32_t*)(sm + SM_AL + row * 528 + c * 2) = l;
        }
    } else if (tid < 128 + 27) {
        int q = tid - 128, g = q / 9, jj = q - 9 * g;
        if (g < nb)
            g_cat[(size_t)(b0 + g) * NCAT + NE + jj] =
                obs[(size_t)(b0 + g) * OBS_STRIDE + jj];
    }
    __syncthreads();

    float acc[32][4];
    #pragma unroll
    for (int f = 0; f < 32; f++)
        acc[f][0] = acc[f][1] = acc[f][2] = acc[f][3] = 0.f;
    layer_mma<256, 32>(sm, smu, tid, gW1h, gW1l, sb1, 256, acc);
    epi_store<256>(sm, tid, acc);

    #pragma unroll
    for (int f = 0; f < 32; f++)
        acc[f][0] = acc[f][1] = acc[f][2] = acc[f][3] = 0.f;
    layer_mma<256, 256>(sm, smu, tid, gW2h, gW2l, sb2, 256, acc);
    epi_store<256>(sm, tid, acc);

    #pragma unroll
    for (int f = 0; f < 16; f++)
        acc[f][0] = acc[f][1] = acc[f][2] = acc[f][3] = 0.f;
    layer_mma<128, 256>(sm, smu, tid, gW3h, gW3l, sb3, 128, acc);
    epi_final(sm, tid, acc, b0, nb);
}

// ---------------------------------------------------------------------------
// heads: cat(137)->256->256->{23,1} via mma.sync; 128 batch rows per CTA
// ---------------------------------------------------------------------------
__device__ __forceinline__ void build_cat_A(char* sm, int tid, int rb)
{
    float* red = (float*)(sm + SM_RED);
    for (int i = tid; i < 128 * NCAT; i += 256) {
        int r = i / NCAT, c = i - r * NCAT;
        red[r * 140 + c] = g_cat[(size_t)(rb + r) * NCAT + c];
    }
    __syncthreads();
    if (tid < 128) {
        const int row = tid;
        #pragma unroll
        for (int k = 0; k < 160; k += 2) {
            float v0 = (k     < NCAT) ? red[row * 140 + k]     : 0.f;
            float v1 = (k + 1 < NCAT) ? red[row * 140 + k + 1] : 0.f;
            uint32_t h, l;
            split2(v0, v1, h, l);
            *(uint32_t*)(sm + SM_AH + row * 528 + k * 2) = h;
            *(uint32_t*)(sm + SM_AL + row * 528 + k * 2) = l;
        }
    }
    __syncthreads();
}

__global__ __launch_bounds__(256, 1) void heads_mma_kernel(
    float* __restrict__ out,
    const float* __restrict__ ab1, const float* __restrict__ ab2,
    const float* __restrict__ ab3,
    const float* __restrict__ vb1, const float* __restrict__ vb2,
    const float* __restrict__ vW3, const float* __restrict__ vb3)
{
    extern __shared__ char sm[];
    const uint32_t smu = smem_u32(sm);
    const int tid = threadIdx.x;
    const int lane = tid & 31, w = tid >> 5;
    const int rb = blockIdx.x * 128;

    float acc[32][4];

    // ===== action branch =====
    build_cat_A(sm, tid, rb);
    #pragma unroll
    for (int f = 0; f < 32; f++)
        acc[f][0] = acc[f][1] = acc[f][2] = acc[f][3] = 0.f;
    layer_mma<256, 160>(sm, smu, tid, hA1h, hA1l, ab1, 256, acc);
    epi_store<256>(sm, tid, acc);

    #pragma unroll
    for (int f = 0; f < 32; f++)
        acc[f][0] = acc[f][1] = acc[f][2] = acc[f][3] = 0.f;
    layer_mma<256, 256>(sm, smu, tid, hA2h, hA2l, ab2, 256, acc);
    epi_store<256>(sm, tid, acc);

    {
        float acc3[4][4];
        #pragma unroll
        for (int f = 0; f < 4; f++)
            acc3[f][0] = acc3[f][1] = acc3[f][2] = acc3[f][3] = 0.f;
        layer_mma<32, 256>(sm, smu, tid, hA3h, hA3l, ab3, NOUT, acc3);
        const float* sb = (const float*)(sm + SM_BIAS);
        const int r0 = 16 * w + (lane >> 2);
        #pragma unroll
        for (int f = 0; f < 4; f++) {
            int c = 8 * f + 2 * (lane & 3);
            if (c < NOUT) {
                out[(size_t)(rb + r0) * NOUT + c]     = acc3[f][0] + sb[c];
                out[(size_t)(rb + r0 + 8) * NOUT + c] = acc3[f][2] + sb[c];
            }
            if (c + 1 < NOUT) {
                out[(size_t)(rb + r0) * NOUT + c + 1]     = acc3[f][1] + sb[c + 1];
                out[(size_t)(rb + r0 + 8) * NOUT + c + 1] = acc3[f][3] + sb[c + 1];
            }
        }
    }

    // ===== value branch =====
    build_cat_A(sm, tid, rb);
    #pragma unroll
    for (int f = 0; f < 32; f++)
        acc[f][0] = acc[f][1] = acc[f][2] = acc[f][3] = 0.f;
    layer_mma<256, 160>(sm, smu, tid, hV1h, hV1l, vb1, 256, acc);
    epi_store<256>(sm, tid, acc);

    #pragma unroll
    for (int f = 0; f < 32; f++)
        acc[f][0] = acc[f][1] = acc[f][2] = acc[f][3] = 0.f;
    layer_mma<256, 256>(sm, smu, tid, hV2h, hV2l, vb2, 256, acc);
    epi_store<256>(sm, tid, acc);

    // v3: dot(v2act, vW3) per row; 2 threads per row
    {
        float* sw = (float*)(sm + SM_BIAS);
        for (int i = tid; i < 256; i += 256) sw[i] = vW3[i];
        __syncthreads();
        const int r = tid >> 1, half = tid & 1;
        float a = 0.f;
        const char* rowp = sm + r * 528;
        #pragma unroll 4
        for (int k = half * 128; k < half * 128 + 128; k++) {
            float h = __bfloat162float(*(const __nv_bfloat16*)(rowp + SM_AH + k * 2));
            float l = __bfloat162float(*(const __nv_bfloat16*)(rowp + SM_AL + k * 2));
            a = fmaf(h + l, sw[k], a);
        }
        a += __shfl_xor_sync(0xffffffffu, a, 1);
        if (half == 0)
            out[(size_t)NB * NOUT + rb + r] = a + vb3[0];
    }
}

// ---------------------------------------------------------------------------
extern "C" void kernel_launch(void* const* d_in, const int* in_sizes, int n_in,
                              void* d_out, int out_size)
{
    const float* obs = (const float*)d_in[0];
    const float* sW1 = (const float*)d_in[1];
    const float* sb1 = (const float*)d_in[2];
    const float* sW2 = (const float*)d_in[3];
    const float* sb2 = (const float*)d_in[4];
    const float* sW3 = (const float*)d_in[5];
    const float* sb3 = (const float*)d_in[6];
    const float* aW1 = (const float*)d_in[7];
    const float* ab1 = (const float*)d_in[8];
    const float* aW2 = (const float*)d_in[9];
    const float* ab2 = (const float*)d_in[10];
    const float* aW3 = (const float*)d_in[11];
    const float* ab3 = (const float*)d_in[12];
    const float* vW1 = (const float*)d_in[13];
    const float* vb1 = (const float*)d_in[14];
    const float* vW2 = (const float*)d_in[15];
    const float* vb2 = (const float*)d_in[16];
    const float* vW3 = (const float*)d_in[17];
    const float* vb3 = (const float*)d_in[18];
    float* out = (float*)d_out;

    cudaFuncSetAttribute(embed_mma_kernel, cudaFuncAttributeMaxDynamicSharedMemorySize,
                         SM_TOTAL);
    cudaFuncSetAttribute(heads_mma_kernel, cudaFuncAttributeMaxDynamicSharedMemorySize,
                         SM_TOTAL);

    // prep: (src, sel, Nn, Npad, Kk, Kpad); blocks = ceil(Npad*Kpad/2/256)
    prep_w<<<16,  256>>>(sW1, 0, 256, 256, NF,   32);
    prep_w<<<128, 256>>>(sW2, 1, 256, 256, 256, 256);
    prep_w<<<64,  256>>>(sW3, 2, 128, 128, 256, 256);
    prep_w<<<80,  256>>>(aW1, 3, 256, 256, NCAT, 160);
    prep_w<<<128, 256>>>(aW2, 4, 256, 256, 256, 256);
    prep_w<<<16,  256>>>(aW3, 5, NOUT, 32, 256, 256);
    prep_w<<<80,  256>>>(vW1, 6, 256, 256, NCAT, 160);
    prep_w<<<128, 256>>>(vW2, 7, 256, 256, 256, 256);

    embed_mma_kernel<<<(NB + GBATCH - 1) / GBATCH, 256, SM_TOTAL>>>(obs, sb1, sb2, sb3);
    heads_mma_kernel<<<NB / 128, 256, SM_TOTAL>>>(out, ab1, ab2, ab3,
                                                  vb1, vb2, vW3, vb3);
}

// round 9
// speedup vs baseline: 4.6782x; 1.1651x over previous
#include <cuda_runtime.h>
#include <cuda_bf16.h>
#include <cstdint>

#define NB    16384
#define NS    37
#define NF    17
#define NOWN  9
#define NH    256
#define NE    128
#define NCAT  137
#define NOUT  23

#define GBATCH 3
#define OBS_STRIDE ((NS + 1) * NF)

// ---------------------------------------------------------------------------
// device globals
// ---------------------------------------------------------------------------
__device__ float g_cat[(size_t)NB * NCAT];

// prepped weights, bf16 hi/lo split, layout [chunk][N rows][64B row],
// quads of each row rotated by (n>>1)&3 for conflict-free LDSM at 64B stride.
__device__ __align__(16) __nv_bfloat16 gW1h[1 * 256 * 32], gW1l[1 * 256 * 32];
__device__ __align__(16) __nv_bfloat16 gW2h[8 * 256 * 32], gW2l[8 * 256 * 32];
__device__ __align__(16) __nv_bfloat16 gW3h[8 * 128 * 32], gW3l[8 * 128 * 32];
__device__ __align__(16) __nv_bfloat16 hA1h[5 * 256 * 32], hA1l[5 * 256 * 32];
__device__ __align__(16) __nv_bfloat16 hA2h[8 * 256 * 32], hA2l[8 * 256 * 32];
__device__ __align__(16) __nv_bfloat16 hA3h[8 * 32 * 32],  hA3l[8 * 32 * 32];
__device__ __align__(16) __nv_bfloat16 hV1h[5 * 256 * 32], hV1l[5 * 256 * 32];
__device__ __align__(16) __nv_bfloat16 hV2h[8 * 256 * 32], hV2l[8 * 256 * 32];

// ---------------------------------------------------------------------------
// smem layout (bytes). A rows stride 528 (conflict-free LDSM).
// B stages are linear [hi Nn*64 | lo Nn*64], filled by cp.async.bulk.
// ---------------------------------------------------------------------------
#define SM_BIAS  0                       // 1024B
#define SM_MASK  1024                    // 512B
#define SM_MBAR  1536                    // 2 x 8B mbarriers
#define SM_AH    2048
#define ALOFF    67584                   // 128 * 528
#define SM_AL    (SM_AH + ALOFF)
#define SM_B0    (SM_AL + ALOFF)         // 137216 (128B aligned)
#define BSTG     32768                   // one stage (max Nn=256: 2*16KB)
#define SM_RED   SM_B0                   // alias (used only when pipe drained)
#define SM_TOTAL (SM_B0 + 71680)         // 208896: covers 2*BSTG and red bufs

// ---------------------------------------------------------------------------
// helpers
// ---------------------------------------------------------------------------
__device__ __forceinline__ uint32_t smem_u32(const void* p) {
    uint32_t a;
    asm("{ .reg .u64 t; cvta.to.shared.u64 t, %1; cvt.u32.u64 %0, t; }"
        : "=r"(a) : "l"(p));
    return a;
}

__device__ __forceinline__ void mma16816(float* d, const uint32_t* a, const uint32_t* b) {
    asm volatile(
        "mma.sync.aligned.m16n8k16.row.col.f32.bf16.bf16.f32 "
        "{%0,%1,%2,%3}, {%4,%5,%6,%7}, {%8,%9}, {%0,%1,%2,%3};"
        : "+f"(d[0]), "+f"(d[1]), "+f"(d[2]), "+f"(d[3])
        : "r"(a[0]), "r"(a[1]), "r"(a[2]), "r"(a[3]), "r"(b[0]), "r"(b[1]));
}

__device__ __forceinline__ void ldsm4(uint32_t* r, uint32_t addr) {
    asm volatile("ldmatrix.sync.aligned.m8n8.x4.shared.b16 {%0,%1,%2,%3}, [%4];"
        : "=r"(r[0]), "=r"(r[1]), "=r"(r[2]), "=r"(r[3]) : "r"(addr));
}

__device__ __forceinline__ void split2(float v0, float v1, uint32_t& h, uint32_t& l) {
    __nv_bfloat162 hh, ll;
    hh.x = __float2bfloat16(v0);
    hh.y = __float2bfloat16(v1);
    ll.x = __float2bfloat16(v0 - __bfloat162float(hh.x));
    ll.y = __float2bfloat16(v1 - __bfloat162float(hh.y));
    h = *(uint32_t*)&hh;
    l = *(uint32_t*)&ll;
}

#define MBAR_INIT(mbar, cnt) \
    asm volatile("mbarrier.init.shared.b64 [%0], %1;" :: "r"(mbar), "r"(cnt) : "memory")
#define MBAR_EXPECT_TX(mbar, tx) \
    asm volatile("mbarrier.arrive.expect_tx.shared.b64 _, [%0], %1;" \
                 :: "r"(mbar), "r"(tx) : "memory")
#define BULK_G2S(dst, src, sz, mbar) \
    asm volatile("cp.async.bulk.shared::cluster.global.mbarrier::complete_tx::bytes " \
                 "[%0], [%1], %2, [%3];" \
                 :: "r"(dst), "l"(src), "r"(sz), "r"(mbar) : "memory")

__device__ __forceinline__ void mbar_wait(uint32_t mbar, uint32_t parity) {
    asm volatile(
        "{\n\t.reg .pred P1;\n\t"
        "LAB_W_%=:\n\t"
        "mbarrier.try_wait.parity.acquire.cta.shared::cta.b64 P1, [%0], %1, 0x989680;\n\t"
        "@P1 bra LAB_D_%=;\n\t"
        "bra LAB_W_%=;\n\t"
        "LAB_D_%=:\n\t}"
        :: "r"(mbar), "r"(parity) : "memory");
}

// issue one weight chunk (hi+lo) into a stage via bulk copy. call from tid 0.
__device__ __forceinline__ void issue_bulk(
    uint32_t smu, const __nv_bfloat16* gwh, const __nv_bfloat16* gwl,
    int chunk, int Nn, int stage)
{
    uint32_t mbar = smu + SM_MBAR + (uint32_t)stage * 8;
    uint32_t part = (uint32_t)(Nn * 64);
    MBAR_EXPECT_TX(mbar, 2 * part);
    uint32_t dst = smu + SM_B0 + (uint32_t)stage * BSTG;
    const char* sh = (const char*)gwh + (size_t)chunk * part;
    const char* sl = (const char*)gwl + (size_t)chunk * part;
    BULK_G2S(dst, sh, part, mbar);
    BULK_G2S(dst + part, sl, part, mbar);
}

// ---------------------------------------------------------------------------
// prep: fp32 [K][N] weights -> bf16 hi/lo [chunk][n][64B], quad-rotated rows
// ---------------------------------------------------------------------------
__global__ void prep_w(const float* __restrict__ src, int sel,
                       int Nn, int Npad, int Kk, int Kpad)
{
    __nv_bfloat16 *dh, *dl;
    switch (sel) {
        case 0: dh = gW1h; dl = gW1l; break;
        case 1: dh = gW2h; dl = gW2l; break;
        case 2: dh = gW3h; dl = gW3l; break;
        case 3: dh = hA1h; dl = hA1l; break;
        case 4: dh = hA2h; dl = hA2l; break;
        case 5: dh = hA3h; dl = hA3l; break;
        case 6: dh = hV1h; dl = hV1l; break;
        default: dh = hV2h; dl = hV2l; break;
    }
    int idx = blockIdx.x * 256 + threadIdx.x;
    int kh = Kpad >> 1;
    if (idx >= Npad * kh) return;
    int n = idx / kh, k = (idx - n * kh) * 2;
    float x0 = (n < Nn && k     < Kk) ? src[k * Nn + n]       : 0.f;
    float x1 = (n < Nn && k + 1 < Kk) ? src[(k + 1) * Nn + n] : 0.f;
    int ch = k >> 5, kk = k & 31;
    int qphys = ((kk >> 3) + ((n >> 1) & 3)) & 3;
    size_t off = (size_t)ch * Npad * 64 + (size_t)n * 64 + qphys * 16 + (kk & 7) * 2;
    __nv_bfloat162 h, l;
    h.x = __float2bfloat16(x0);
    h.y = __float2bfloat16(x1);
    l.x = __float2bfloat16(x0 - __bfloat162float(h.x));
    l.y = __float2bfloat16(x1 - __bfloat162float(h.y));
    *(__nv_bfloat162*)((char*)dh + off) = h;
    *(__nv_bfloat162*)((char*)dl + off) = l;
}

// ---------------------------------------------------------------------------
// one layer: C[128,Nn] += A[128,Kp]*W, split-bf16 x3, bulk double-buffered
// pph: per-stage mbarrier phase (persistent across layers within a kernel)
// ---------------------------------------------------------------------------
template<int Nn, int Kp>
__device__ __forceinline__ void layer_mma(
    char* sm, uint32_t smu, int tid,
    const __nv_bfloat16* __restrict__ gwh,
    const __nv_bfloat16* __restrict__ gwl,
    const float* __restrict__ bias, int nbias,
    float (*acc)[4], int2& pph)
{
    constexpr int NCH = Kp / 32;
    const int lane = tid & 31;
    const int w = tid >> 5;
    const int j = lane >> 3, wi = lane & 7;
    const uint32_t aaddr = smu + SM_AH +
        (uint32_t)((16 * w + (j & 1) * 8 + wi) * 528 + ((j >> 1) * 8) * 2);
    // B addressing: row nb8 within 16-row group, 64B rows, rotated quads
    const int nb8 = (j >> 1) * 8 + wi;
    const int rot = (nb8 >> 1) & 3;
    const uint32_t rowoff = (uint32_t)(nb8 * 64);
    const uint32_t q0 = (uint32_t)(((((j & 1) + rot)) & 3) * 16);
    const uint32_t q1 = (uint32_t)(((((j & 1) + rot + 2)) & 3) * 16);

    float* sb = (float*)(sm + SM_BIAS);
    for (int i = tid; i < nbias; i += 256) sb[i] = bias[i];

    if (tid == 0) issue_bulk(smu, gwh, gwl, 0, Nn, 0);

    #pragma unroll 1
    for (int kc = 0; kc < NCH; kc++) {
        if (tid == 0 && kc + 1 < NCH)
            issue_bulk(smu, gwh, gwl, kc + 1, Nn, (kc + 1) & 1);

        const int st = kc & 1;
        int ph = st ? pph.y : pph.x;
        mbar_wait(smu + SM_MBAR + (uint32_t)st * 8, (uint32_t)(ph & 1));
        if (st) pph.y = ph ^ 1; else pph.x = ph ^ 1;

        const uint32_t bbase = smu + SM_B0 + (uint32_t)(st * BSTG) + rowoff;
        #pragma unroll
        for (int ks = 0; ks < 2; ks++) {
            uint32_t ah[4], al[4];
            uint32_t ao = aaddr + (uint32_t)((kc * 32 + ks * 16) * 2);
            ldsm4(ah, ao);
            ldsm4(al, ao + ALOFF);
            const uint32_t qo = ks ? q1 : q0;
            #pragma unroll
            for (int g = 0; g < Nn / 16; g++) {
                uint32_t bh[4], bl[4];
                uint32_t ba = bbase + (uint32_t)(g * 1024) + qo;
                ldsm4(bh, ba);
                ldsm4(bl, ba + (uint32_t)(Nn * 64));
                mma16816(acc[2 * g],     ah, bh);
                mma16816(acc[2 * g + 1], ah, bh + 2);
                mma16816(acc[2 * g],     ah, bl);
                mma16816(acc[2 * g + 1], ah, bl + 2);
                mma16816(acc[2 * g],     al, bh);
                mma16816(acc[2 * g + 1], al, bh + 2);
            }
        }
        __syncthreads();   // all warps done with stage st before it is refilled
    }
}

// epilogue: relu(acc + bias) -> split bf16 hi/lo into A tiles
template<int Nn>
__device__ __forceinline__ void epi_store(char* sm, int tid, float (*acc)[4])
{
    const int lane = tid & 31, w = tid >> 5;
    const int r0 = 16 * w + (lane >> 2);
    const float* sb = (const float*)(sm + SM_BIAS);
    #pragma unroll
    for (int f = 0; f < Nn / 8; f++) {
        int c = 8 * f + 2 * (lane & 3);
        float b0 = sb[c], b1 = sb[c + 1];
        uint32_t h, l;
        split2(fmaxf(acc[f][0] + b0, 0.f), fmaxf(acc[f][1] + b1, 0.f), h, l);
        *(uint32_t*)(sm + SM_AH + r0 * 528 + c * 2) = h;
        *(uint32_t*)(sm + SM_AL + r0 * 528 + c * 2) = l;
        split2(fmaxf(acc[f][2] + b0, 0.f), fmaxf(acc[f][3] + b1, 0.f), h, l);
        *(uint32_t*)(sm + SM_AH + (r0 + 8) * 528 + c * 2) = h;
        *(uint32_t*)(sm + SM_AL + (r0 + 8) * 528 + c * 2) = l;
    }
    __syncthreads();
}

// embed final epilogue: mask * relu(acc + bias), masked segment sum -> g_cat
__device__ __forceinline__ void epi_final(char* sm, int tid, float (*acc)[4],
                                          int b0batch, int nb)
{
    const int lane = tid & 31, w = tid >> 5;
    const int r0 = 16 * w + (lane >> 2);
    const float* sb = (const float*)(sm + SM_BIAS);
    const float* mk = (const float*)(sm + SM_MASK);
    const float m0 = mk[r0], m1 = mk[r0 + 8];
    #pragma unroll
    for (int f = 0; f < 16; f++) {
        int c = 8 * f + 2 * (lane & 3);
        float b0 = sb[c], b1 = sb[c + 1];
        float2 v;
        v.x = m0 * fmaxf(acc[f][0] + b0, 0.f);
        v.y = m0 * fmaxf(acc[f][1] + b1, 0.f);
        *(float2*)(sm + SM_RED + r0 * 528 + c * 4) = v;
        v.x = m1 * fmaxf(acc[f][2] + b0, 0.f);
        v.y = m1 * fmaxf(acc[f][3] + b1, 0.f);
        *(float2*)(sm + SM_RED + (r0 + 8) * 528 + c * 4) = v;
    }
    __syncthreads();
    const float* red = (const float*)(sm + SM_RED);
    for (int p = tid; p < 3 * 128; p += 256) {
        int bg = p >> 7, c = p & 127;
        if (bg < nb) {
            float s = 0.f;
            #pragma unroll
            for (int i = 0; i < NS; i++)
                s += red[(bg * 37 + i) * 132 + c];
            g_cat[(size_t)(b0batch + bg) * NCAT + c] = s;
        }
    }
}

// ---------------------------------------------------------------------------
// embed: token MLP 17->256->256->128 via mma.sync, masked segment sum
// ---------------------------------------------------------------------------
__global__ __launch_bounds__(256, 1) void embed_mma_kernel(
    const float* __restrict__ obs,
    const float* __restrict__ sb1, const float* __restrict__ sb2,
    const float* __restrict__ sb3)
{
    extern __shared__ char sm[];
    const uint32_t smu = smem_u32(sm);
    const int tid = threadIdx.x;
    const int b0 = blockIdx.x * GBATCH;
    const int nb = (NB - b0 < GBATCH) ? (NB - b0) : GBATCH;

    if (tid == 0) {
        MBAR_INIT(smu + SM_MBAR, 1);
        MBAR_INIT(smu + SM_MBAR + 8, 1);
    }
    int2 pph = make_int2(0, 0);

    float* maskv = (float*)(sm + SM_MASK);
    if (tid < 128) {
        const int row = tid;
        const int g = row / 37, s = row - g * 37;
        const bool valid = (row < 111) && (g < nb);
        float x[32];
        #pragma unroll
        for (int f = 0; f < 32; f++) x[f] = 0.f;
        float sabs = 0.f;
        if (valid) {
            const float* p = obs + (size_t)(b0 + g) * OBS_STRIDE + (size_t)(s + 1) * NF;
            #pragma unroll
            for (int f = 0; f < NF; f++) { x[f] = p[f]; sabs += fabsf(x[f]); }
        }
        maskv[row] = (valid && sabs != 0.f) ? 1.f : 0.f;
        #pragma unroll
        for (int c = 0; c < 32; c += 2) {
            uint32_t h, l;
            split2(x[c], x[c + 1], h, l);
            *(uint32_t*)(sm + SM_AH + row * 528 + c * 2) = h;
            *(uint32_t*)(sm + SM_AL + row * 528 + c * 2) = l;
        }
    } else if (tid < 128 + 27) {
        int q = tid - 128, g = q / 9, jj = q - 9 * g;
        if (g < nb)
            g_cat[(size_t)(b0 + g) * NCAT + NE + jj] =
                obs[(size_t)(b0 + g) * OBS_STRIDE + jj];
    }
    __syncthreads();

    float acc[32][4];
    #pragma unroll
    for (int f = 0; f < 32; f++)
        acc[f][0] = acc[f][1] = acc[f][2] = acc[f][3] = 0.f;
    layer_mma<256, 32>(sm, smu, tid, gW1h, gW1l, sb1, 256, acc, pph);
    epi_store<256>(sm, tid, acc);

    #pragma unroll
    for (int f = 0; f < 32; f++)
        acc[f][0] = acc[f][1] = acc[f][2] = acc[f][3] = 0.f;
    layer_mma<256, 256>(sm, smu, tid, gW2h, gW2l, sb2, 256, acc, pph);
    epi_store<256>(sm, tid, acc);

    #pragma unroll
    for (int f = 0; f < 16; f++)
        acc[f][0] = acc[f][1] = acc[f][2] = acc[f][3] = 0.f;
    layer_mma<128, 256>(sm, smu, tid, gW3h, gW3l, sb3, 128, acc, pph);
    epi_final(sm, tid, acc, b0, nb);
}

// ---------------------------------------------------------------------------
// heads: cat(137)->256->256->{23,1} via mma.sync; 128 batch rows per CTA
// ---------------------------------------------------------------------------
__device__ __forceinline__ void build_cat_A(char* sm, int tid, int rb)
{
    float* red = (float*)(sm + SM_RED);
    for (int i = tid; i < 128 * NCAT; i += 256) {
        int r = i / NCAT, c = i - r * NCAT;
        red[r * 140 + c] = g_cat[(size_t)(rb + r) * NCAT + c];
    }
    __syncthreads();
    if (tid < 128) {
        const int row = tid;
        #pragma unroll
        for (int k = 0; k < 160; k += 2) {
            float v0 = (k     < NCAT) ? red[row * 140 + k]     : 0.f;
            float v1 = (k + 1 < NCAT) ? red[row * 140 + k + 1] : 0.f;
            uint32_t h, l;
            split2(v0, v1, h, l);
            *(uint32_t*)(sm + SM_AH + row * 528 + k * 2) = h;
            *(uint32_t*)(sm + SM_AL + row * 528 + k * 2) = l;
        }
    }
    __syncthreads();
}

__global__ __launch_bounds__(256, 1) void heads_mma_kernel(
    float* __restrict__ out,
    const float* __restrict__ ab1, const float* __restrict__ ab2,
    const float* __restrict__ ab3,
    const float* __restrict__ vb1, const float* __restrict__ vb2,
    const float* __restrict__ vW3, const float* __restrict__ vb3)
{
    extern __shared__ char sm[];
    const uint32_t smu = smem_u32(sm);
    const int tid = threadIdx.x;
    const int lane = tid & 31, w = tid >> 5;
    const int rb = blockIdx.x * 128;

    if (tid == 0) {
        MBAR_INIT(smu + SM_MBAR, 1);
        MBAR_INIT(smu + SM_MBAR + 8, 1);
    }
    int2 pph = make_int2(0, 0);

    float acc[32][4];

    // ===== action branch =====
    build_cat_A(sm, tid, rb);
    #pragma unroll
    for (int f = 0; f < 32; f++)
        acc[f][0] = acc[f][1] = acc[f][2] = acc[f][3] = 0.f;
    layer_mma<256, 160>(sm, smu, tid, hA1h, hA1l, ab1, 256, acc, pph);
    epi_store<256>(sm, tid, acc);

    #pragma unroll
    for (int f = 0; f < 32; f++)
        acc[f][0] = acc[f][1] = acc[f][2] = acc[f][3] = 0.f;
    layer_mma<256, 256>(sm, smu, tid, hA2h, hA2l, ab2, 256, acc, pph);
    epi_store<256>(sm, tid, acc);

    {
        float acc3[4][4];
        #pragma unroll
        for (int f = 0; f < 4; f++)
            acc3[f][0] = acc3[f][1] = acc3[f][2] = acc3[f][3] = 0.f;
        layer_mma<32, 256>(sm, smu, tid, hA3h, hA3l, ab3, NOUT, acc3, pph);
        const float* sb = (const float*)(sm + SM_BIAS);
        const int r0 = 16 * w + (lane >> 2);
        #pragma unroll
        for (int f = 0; f < 4; f++) {
            int c = 8 * f + 2 * (lane & 3);
            if (c < NOUT) {
                out[(size_t)(rb + r0) * NOUT + c]     = acc3[f][0] + sb[c];
                out[(size_t)(rb + r0 + 8) * NOUT + c] = acc3[f][2] + sb[c];
            }
            if (c + 1 < NOUT) {
                out[(size_t)(rb + r0) * NOUT + c + 1]     = acc3[f][1] + sb[c + 1];
                out[(size_t)(rb + r0 + 8) * NOUT + c + 1] = acc3[f][3] + sb[c + 1];
            }
        }
        __syncthreads();
    }

    // ===== value branch =====
    build_cat_A(sm, tid, rb);
    #pragma unroll
    for (int f = 0; f < 32; f++)
        acc[f][0] = acc[f][1] = acc[f][2] = acc[f][3] = 0.f;
    layer_mma<256, 160>(sm, smu, tid, hV1h, hV1l, vb1, 256, acc, pph);
    epi_store<256>(sm, tid, acc);

    #pragma unroll
    for (int f = 0; f < 32; f++)
        acc[f][0] = acc[f][1] = acc[f][2] = acc[f][3] = 0.f;
    layer_mma<256, 256>(sm, smu, tid, hV2h, hV2l, vb2, 256, acc, pph);
    epi_store<256>(sm, tid, acc);

    // v3: dot(v2act, vW3) per row; 2 threads per row
    {
        float* sw = (float*)(sm + SM_BIAS);
        for (int i = tid; i < 256; i += 256) sw[i] = vW3[i];
        __syncthreads();
        const int r = tid >> 1, half = tid & 1;
        float a = 0.f;
        const char* rowp = sm + r * 528;
        #pragma unroll 4
        for (int k = half * 128; k < half * 128 + 128; k++) {
            float h = __bfloat162float(*(const __nv_bfloat16*)(rowp + SM_AH + k * 2));
            float l = __bfloat162float(*(const __nv_bfloat16*)(rowp + SM_AL + k * 2));
            a = fmaf(h + l, sw[k], a);
        }
        a += __shfl_xor_sync(0xffffffffu, a, 1);
        if (half == 0)
            out[(size_t)NB * NOUT + rb + r] = a + vb3[0];
    }
}

// ---------------------------------------------------------------------------
extern "C" void kernel_launch(void* const* d_in, const int* in_sizes, int n_in,
                              void* d_out, int out_size)
{
    const float* obs = (const float*)d_in[0];
    const float* sW1 = (const float*)d_in[1];
    const float* sb1 = (const float*)d_in[2];
    const float* sW2 = (const float*)d_in[3];
    const float* sb2 = (const float*)d_in[4];
    const float* sW3 = (const float*)d_in[5];
    const float* sb3 = (const float*)d_in[6];
    const float* aW1 = (const float*)d_in[7];
    const float* ab1 = (const float*)d_in[8];
    const float* aW2 = (const float*)d_in[9];
    const float* ab2 = (const float*)d_in[10];
    const float* aW3 = (const float*)d_in[11];
    const float* ab3 = (const float*)d_in[12];
    const float* vW1 = (const float*)d_in[13];
    const float* vb1 = (const float*)d_in[14];
    const float* vW2 = (const float*)d_in[15];
    const float* vb2 = (const float*)d_in[16];
    const float* vW3 = (const float*)d_in[17];
    const float* vb3 = (const float*)d_in[18];
    float* out = (float*)d_out;

    cudaFuncSetAttribute(embed_mma_kernel, cudaFuncAttributeMaxDynamicSharedMemorySize,
                         SM_TOTAL);
    cudaFuncSetAttribute(heads_mma_kernel, cudaFuncAttributeMaxDynamicSharedMemorySize,
                         SM_TOTAL);

    // prep: (src, sel, Nn, Npad, Kk, Kpad); blocks = ceil(Npad*Kpad/2/256)
    prep_w<<<16,  256>>>(sW1, 0, 256, 256, NF,   32);
    prep_w<<<128, 256>>>(sW2, 1, 256, 256, 256, 256);
    prep_w<<<64,  256>>>(sW3, 2, 128, 128, 256, 256);
    prep_w<<<80,  256>>>(aW1, 3, 256, 256, NCAT, 160);
    prep_w<<<128, 256>>>(aW2, 4, 256, 256, 256, 256);
    prep_w<<<16,  256>>>(aW3, 5, NOUT, 32, 256, 256);
    prep_w<<<80,  256>>>(vW1, 6, 256, 256, NCAT, 160);
    prep_w<<<128, 256>>>(vW2, 7, 256, 256, 256, 256);

    embed_mma_kernel<<<(NB + GBATCH - 1) / GBATCH, 256, SM_TOTAL>>>(obs, sb1, sb2, sb3);
    heads_mma_kernel<<<NB / 128, 256, SM_TOTAL>>>(out, ab1, ab2, ab3,
                                                  vb1, vb2, vW3, vb3);
}

// round 12
// speedup vs baseline: 6.0166x; 1.2861x over previous
#include <cuda_runtime.h>
#include <cuda_bf16.h>
#include <cstdint>

#define NB    16384
#define NS    37
#define NF    17
#define NOWN  9
#define NH    256
#define NE    128
#define NCAT  137
#define NOUT  23

#define NBCTA 4736                       // max embed CTAs (606208 / 128)
#define MAXSEG 32

// ---------------------------------------------------------------------------
// device globals
// ---------------------------------------------------------------------------
__device__ float g_cat[(size_t)NB * NCAT];
__device__ int g_cnt[NB];
__device__ int g_off[NB + 1];
__device__ unsigned char g_sidx[NB * NS];
__device__ float g_part[(size_t)NBCTA * MAXSEG * 128];

// prepped weights, bf16 hi/lo split, layout [chunk][N rows][64B row],
// quads of each row rotated by (n>>1)&3 for conflict-free LDSM at 64B stride.
__device__ __align__(16) __nv_bfloat16 gW1h[1 * 256 * 32], gW1l[1 * 256 * 32];
__device__ __align__(16) __nv_bfloat16 gW2h[8 * 256 * 32], gW2l[8 * 256 * 32];
__device__ __align__(16) __nv_bfloat16 gW3h[8 * 128 * 32], gW3l[8 * 128 * 32];
__device__ __align__(16) __nv_bfloat16 hA1h[5 * 256 * 32], hA1l[5 * 256 * 32];
__device__ __align__(16) __nv_bfloat16 hA2h[8 * 256 * 32], hA2l[8 * 256 * 32];
__device__ __align__(16) __nv_bfloat16 hA3h[8 * 32 * 32],  hA3l[8 * 32 * 32];
__device__ __align__(16) __nv_bfloat16 hV1h[5 * 256 * 32], hV1l[5 * 256 * 32];
__device__ __align__(16) __nv_bfloat16 hV2h[8 * 256 * 32], hV2l[8 * 256 * 32];

// ---------------------------------------------------------------------------
// smem layout (bytes). A rows stride 528 (conflict-free LDSM).
// B stages are linear [hi Nn*64 | lo Nn*64], filled by cp.async.bulk.
// ---------------------------------------------------------------------------
#define SM_BIAS  0                       // 1024B
#define SM_MBAR  1536                    // 2 x 8B mbarriers
#define SM_AH    2048
#define ALOFF    67584                   // 128 * 528
#define SM_AL    (SM_AH + ALOFF)
#define SM_B0    (SM_AL + ALOFF)         // 137216 (128B aligned)
#define BSTG     32768                   // one stage (max Nn=256: 2*16KB)
#define SM_RED   SM_B0                   // alias (used only when pipe drained)
#define SM_TOTAL (SM_B0 + 71680)         // 208896

// ---------------------------------------------------------------------------
// helpers
// ---------------------------------------------------------------------------
__device__ __forceinline__ uint32_t smem_u32(const void* p) {
    uint32_t a;
    asm("{ .reg .u64 t; cvta.to.shared.u64 t, %1; cvt.u32.u64 %0, t; }"
        : "=r"(a) : "l"(p));
    return a;
}

__device__ __forceinline__ void mma16816(float* d, const uint32_t* a, const uint32_t* b) {
    asm volatile(
        "mma.sync.aligned.m16n8k16.row.col.f32.bf16.bf16.f32 "
        "{%0,%1,%2,%3}, {%4,%5,%6,%7}, {%8,%9}, {%0,%1,%2,%3};"
        : "+f"(d[0]), "+f"(d[1]), "+f"(d[2]), "+f"(d[3])
        : "r"(a[0]), "r"(a[1]), "r"(a[2]), "r"(a[3]), "r"(b[0]), "r"(b[1]));
}

__device__ __forceinline__ void ldsm4(uint32_t* r, uint32_t addr) {
    asm volatile("ldmatrix.sync.aligned.m8n8.x4.shared.b16 {%0,%1,%2,%3}, [%4];"
        : "=r"(r[0]), "=r"(r[1]), "=r"(r[2]), "=r"(r[3]) : "r"(addr));
}

__device__ __forceinline__ void split2(float v0, float v1, uint32_t& h, uint32_t& l) {
    __nv_bfloat162 hh, ll;
    hh.x = __float2bfloat16(v0);
    hh.y = __float2bfloat16(v1);
    ll.x = __float2bfloat16(v0 - __bfloat162float(hh.x));
    ll.y = __float2bfloat16(v1 - __bfloat162float(hh.y));
    h = *(uint32_t*)&hh;
    l = *(uint32_t*)&ll;
}

// ubound-1 over g_off: largest b with g_off[b] <= r  (r < N_tot)
__device__ __forceinline__ int batch_of(int r) {
    int lo = 0, hi = NB + 1;
    while (lo < hi) {
        int m = (lo + hi) >> 1;
        if (__ldg(&g_off[m]) <= r) lo = m + 1; else hi = m;
    }
    return lo - 1;
}

#define MBAR_INIT(mbar, cnt) \
    asm volatile("mbarrier.init.shared.b64 [%0], %1;" :: "r"(mbar), "r"(cnt) : "memory")
#define MBAR_EXPECT_TX(mbar, tx) \
    asm volatile("mbarrier.arrive.expect_tx.shared.b64 _, [%0], %1;" \
                 :: "r"(mbar), "r"(tx) : "memory")
#define BULK_G2S(dst, src, sz, mbar) \
    asm volatile("cp.async.bulk.shared::cluster.global.mbarrier::complete_tx::bytes " \
                 "[%0], [%1], %2, [%3];" \
                 :: "r"(dst), "l"(src), "r"(sz), "r"(mbar) : "memory")

__device__ __forceinline__ void mbar_wait(uint32_t mbar, uint32_t parity) {
    asm volatile(
        "{\n\t.reg .pred P1;\n\t"
        "LAB_W_%=:\n\t"
        "mbarrier.try_wait.parity.acquire.cta.shared::cta.b64 P1, [%0], %1, 0x989680;\n\t"
        "@P1 bra LAB_D_%=;\n\t"
        "bra LAB_W_%=;\n\t"
        "LAB_D_%=:\n\t}"
        :: "r"(mbar), "r"(parity) : "memory");
}

__device__ __forceinline__ void issue_bulk(
    uint32_t smu, const __nv_bfloat16* gwh, const __nv_bfloat16* gwl,
    int chunk, int Nn, int stage)
{
    uint32_t mbar = smu + SM_MBAR + (uint32_t)stage * 8;
    uint32_t part = (uint32_t)(Nn * 64);
    MBAR_EXPECT_TX(mbar, 2 * part);
    uint32_t dst = smu + SM_B0 + (uint32_t)stage * BSTG;
    const char* sh = (const char*)gwh + (size_t)chunk * part;
    const char* sl = (const char*)gwl + (size_t)chunk * part;
    BULK_G2S(dst, sh, part, mbar);
    BULK_G2S(dst + part, sl, part, mbar);
}

// ---------------------------------------------------------------------------
// K0: per-batch token mask -> compact local token list + count; s_own -> g_cat
// ---------------------------------------------------------------------------
__global__ void mask_kernel(const float* __restrict__ obs)
{
    const int b = blockIdx.x;
    const int tid = threadIdx.x, lane = tid & 31, warp = tid >> 5;
    __shared__ unsigned sm_m[2];

    bool nz = false;
    if (tid < NS) {
        const float* p = obs + ((size_t)b * (NS + 1) + tid + 1) * NF;
        float s = 0.f;
        #pragma unroll
        for (int f = 0; f < NF; f++) s += fabsf(p[f]);
        nz = (s != 0.f);
    }
    unsigned m = __ballot_sync(0xffffffffu, nz);
    if (lane == 0) sm_m[warp] = m;
    __syncthreads();
    if (nz) {
        int pos = __popc(m & ((1u << lane) - 1));
        if (warp == 1) pos += __popc(sm_m[0]);
        g_sidx[b * NS + pos] = (unsigned char)tid;
    }
    if (tid == 0)
        g_cnt[b] = __popc(sm_m[0]) + __popc(sm_m[1]);
    if (tid >= 48 && tid < 48 + NOWN)
        g_cat[(size_t)b * NCAT + NE + (tid - 48)] =
            obs[(size_t)b * (NS + 1) * NF + (tid - 48)];
}

// ---------------------------------------------------------------------------
// K1: exclusive scan of g_cnt -> g_off (single block, 1024 thr x 16 each)
// ---------------------------------------------------------------------------
__global__ void scan_kernel()
{
    __shared__ int sm[1024];
    const int t = threadIdx.x;
    int v[16];
    int s = 0;
    #pragma unroll
    for (int i = 0; i < 16; i++) { v[i] = s; s += g_cnt[t * 16 + i]; }
    sm[t] = s;
    __syncthreads();
    for (int d = 1; d < 1024; d <<= 1) {
        int x = (t >= d) ? sm[t - d] : 0;
        __syncthreads();
        sm[t] += x;
        __syncthreads();
    }
    int base = t ? sm[t - 1] : 0;
    #pragma unroll
    for (int i = 0; i < 16; i++) g_off[t * 16 + i] = base + v[i];
    if (t == 1023) g_off[NB] = sm[1023];
}

// ---------------------------------------------------------------------------
// prep (fused): fp32 [K][N] weights -> bf16 hi/lo [chunk][n][64B], quad-rotated
// ---------------------------------------------------------------------------
__global__ void prep_all(const float* __restrict__ sW1, const float* __restrict__ sW2,
                         const float* __restrict__ sW3, const float* __restrict__ aW1,
                         const float* __restrict__ aW2, const float* __restrict__ aW3,
                         const float* __restrict__ vW1, const float* __restrict__ vW2)
{
    const int blk = blockIdx.x;
    const float* src; __nv_bfloat16 *dh, *dl;
    int Nn, Npad, Kk, Kpad, base;
    if      (blk < 16)  { src=sW1; dh=gW1h; dl=gW1l; Nn=256;  Npad=256; Kk=NF;   Kpad=32;  base=0;   }
    else if (blk < 144) { src=sW2; dh=gW2h; dl=gW2l; Nn=256;  Npad=256; Kk=256;  Kpad=256; base=16;  }
    else if (blk < 208) { src=sW3; dh=gW3h; dl=gW3l; Nn=128;  Npad=128; Kk=256;  Kpad=256; base=144; }
    else if (blk < 288) { src=aW1; dh=hA1h; dl=hA1l; Nn=256;  Npad=256; Kk=NCAT; Kpad=160; base=208; }
    else if (blk < 416) { src=aW2; dh=hA2h; dl=hA2l; Nn=256;  Npad=256; Kk=256;  Kpad=256; base=288; }
    else if (blk < 432) { src=aW3; dh=hA3h; dl=hA3l; Nn=NOUT; Npad=32;  Kk=256;  Kpad=256; base=416; }
    else if (blk < 512) { src=vW1; dh=hV1h; dl=hV1l; Nn=256;  Npad=256; Kk=NCAT; Kpad=160; base=432; }
    else                { src=vW2; dh=hV2h; dl=hV2l; Nn=256;  Npad=256; Kk=256;  Kpad=256; base=512; }

    int idx = (blk - base) * 256 + threadIdx.x;
    int kh = Kpad >> 1;
    if (idx >= Npad * kh) return;
    int n = idx / kh, k = (idx - n * kh) * 2;
    float x0 = (n < Nn && k     < Kk) ? src[k * Nn + n]       : 0.f;
    float x1 = (n < Nn && k + 1 < Kk) ? src[(k + 1) * Nn + n] : 0.f;
    int ch = k >> 5, kk = k & 31;
    int qphys = ((kk >> 3) + ((n >> 1) & 3)) & 3;
    size_t off = (size_t)ch * Npad * 64 + (size_t)n * 64 + qphys * 16 + (kk & 7) * 2;
    __nv_bfloat162 h, l;
    h.x = __float2bfloat16(x0);
    h.y = __float2bfloat16(x1);
    l.x = __float2bfloat16(x0 - __bfloat162float(h.x));
    l.y = __float2bfloat16(x1 - __bfloat162float(h.y));
    *(__nv_bfloat162*)((char*)dh + off) = h;
    *(__nv_bfloat162*)((char*)dl + off) = l;
}

// ---------------------------------------------------------------------------
// one layer: C[128,Nn] += A[128,Kp]*W, split-bf16 x3, bulk double-buffered
// ---------------------------------------------------------------------------
template<int Nn, int Kp>
__device__ __forceinline__ void layer_mma(
    char* sm, uint32_t smu, int tid,
    const __nv_bfloat16* __restrict__ gwh,
    const __nv_bfloat16* __restrict__ gwl,
    const float* __restrict__ bias, int nbias,
    float (*acc)[4], int2& pph)
{
    constexpr int NCH = Kp / 32;
    const int lane = tid & 31;
    const int w = tid >> 5;
    const int j = lane >> 3, wi = lane & 7;
    const uint32_t aaddr = smu + SM_AH +
        (uint32_t)((16 * w + (j & 1) * 8 + wi) * 528 + ((j >> 1) * 8) * 2);
    const int nb8 = (j >> 1) * 8 + wi;
    const int rot = (nb8 >> 1) & 3;
    const uint32_t rowoff = (uint32_t)(nb8 * 64);
    const uint32_t q0 = (uint32_t)(((((j & 1) + rot)) & 3) * 16);
    const uint32_t q1 = (uint32_t)(((((j & 1) + rot + 2)) & 3) * 16);

    float* sb = (float*)(sm + SM_BIAS);
    for (int i = tid; i < nbias; i += 256) sb[i] = bias[i];

    if (tid == 0) issue_bulk(smu, gwh, gwl, 0, Nn, 0);

    #pragma unroll 1
    for (int kc = 0; kc < NCH; kc++) {
        if (tid == 0 && kc + 1 < NCH)
            issue_bulk(smu, gwh, gwl, kc + 1, Nn, (kc + 1) & 1);

        const int st = kc & 1;
        int ph = st ? pph.y : pph.x;
        mbar_wait(smu + SM_MBAR + (uint32_t)st * 8, (uint32_t)(ph & 1));
        if (st) pph.y = ph ^ 1; else pph.x = ph ^ 1;

        const uint32_t bbase = smu + SM_B0 + (uint32_t)(st * BSTG) + rowoff;
        #pragma unroll
        for (int ks = 0; ks < 2; ks++) {
            uint32_t ah[4], al[4];
            uint32_t ao = aaddr + (uint32_t)((kc * 32 + ks * 16) * 2);
            ldsm4(ah, ao);
            ldsm4(al, ao + ALOFF);
            const uint32_t qo = ks ? q1 : q0;
            #pragma unroll
            for (int g = 0; g < Nn / 16; g++) {
                uint32_t bh[4], bl[4];
                uint32_t ba = bbase + (uint32_t)(g * 1024) + qo;
                ldsm4(bh, ba);
                ldsm4(bl, ba + (uint32_t)(Nn * 64));
                mma16816(acc[2 * g],     ah, bh);
                mma16816(acc[2 * g + 1], ah, bh + 2);
                mma16816(acc[2 * g],     ah, bl);
                mma16816(acc[2 * g + 1], ah, bl + 2);
                mma16816(acc[2 * g],     al, bh);
                mma16816(acc[2 * g + 1], al, bh + 2);
            }
        }
        __syncthreads();
    }
}

// epilogue: relu(acc + bias) -> split bf16 hi/lo into A tiles
template<int Nn>
__device__ __forceinline__ void epi_store(char* sm, int tid, float (*acc)[4])
{
    const int lane = tid & 31, w = tid >> 5;
    const int r0 = 16 * w + (lane >> 2);
    const float* sb = (const float*)(sm + SM_BIAS);
    #pragma unroll
    for (int f = 0; f < Nn / 8; f++) {
        int c = 8 * f + 2 * (lane & 3);
        float b0 = sb[c], b1 = sb[c + 1];
        uint32_t h, l;
        split2(fmaxf(acc[f][0] + b0, 0.f), fmaxf(acc[f][1] + b1, 0.f), h, l);
        *(uint32_t*)(sm + SM_AH + r0 * 528 + c * 2) = h;
        *(uint32_t*)(sm + SM_AL + r0 * 528 + c * 2) = l;
        split2(fmaxf(acc[f][2] + b0, 0.f), fmaxf(acc[f][3] + b1, 0.f), h, l);
        *(uint32_t*)(sm + SM_AH + (r0 + 8) * 528 + c * 2) = h;
        *(uint32_t*)(sm + SM_AL + (r0 + 8) * 528 + c * 2) = l;
    }
    __syncthreads();
}

// embed final epilogue: relu(acc+bias) -> RED, per-segment partial sums -> g_part
__device__ __forceinline__ void epi_final(char* sm, int tid, float (*acc)[4], int cta)
{
    const int lane = tid & 31, w = tid >> 5;
    const int r0 = 16 * w + (lane >> 2);
    const float* sb = (const float*)(sm + SM_BIAS);
    #pragma unroll
    for (int f = 0; f < 16; f++) {
        int c = 8 * f + 2 * (lane & 3);
        float b0 = sb[c], b1 = sb[c + 1];
        float2 v;
        v.x = fmaxf(acc[f][0] + b0, 0.f);
        v.y = fmaxf(acc[f][1] + b1, 0.f);
        *(float2*)(sm + SM_RED + r0 * 528 + c * 4) = v;
        v.x = fmaxf(acc[f][2] + b0, 0.f);
        v.y = fmaxf(acc[f][3] + b1, 0.f);
        *(float2*)(sm + SM_RED + (r0 + 8) * 528 + c * 4) = v;
    }
    __syncthreads();

    const float* red = (const float*)(sm + SM_RED);
    const int Ntot = g_off[NB];
    const int rbase = cta * 128;
    int rlast = rbase + 127;
    if (rlast > Ntot - 1) rlast = Ntot - 1;
    const int bs = batch_of(rbase);
    const int be = batch_of(rlast);
    int nseg = be - bs + 1;
    if (nseg > MAXSEG) nseg = MAXSEG;
    const int half = tid >> 7, col = tid & 127;
    for (int s2 = half; s2 < nseg; s2 += 2) {
        int b = bs + s2;
        int lo = g_off[b];     if (lo < rbase) lo = rbase;
        int hi = g_off[b + 1]; if (hi > rbase + 128) hi = rbase + 128;
        float a = 0.f;
        for (int r = lo; r < hi; r++)
            a += red[(r - rbase) * 132 + col];
        g_part[((size_t)cta * MAXSEG + s2) * 128 + col] = a;
    }
}

// ---------------------------------------------------------------------------
// K3: per batch, add the (<=2) CTA partials -> g_cat cols 0..127
// ---------------------------------------------------------------------------
__global__ void reduce_cat()
{
    const int b = blockIdx.x * 2 + (threadIdx.x >> 7);
    const int col = threadIdx.x & 127;
    const int lo = g_off[b], hi = g_off[b + 1];
    float v = 0.f;
    if (hi > lo) {
        int c1 = lo >> 7, c2 = (hi - 1) >> 7;
        int s1 = b - batch_of(c1 << 7);
        if (s1 >= 0 && s1 < MAXSEG)
            v = g_part[((size_t)c1 * MAXSEG + s1) * 128 + col];
        if (c2 != c1) {
            int s2 = b - batch_of(c2 << 7);
            if (s2 >= 0 && s2 < MAXSEG)
                v += g_part[((size_t)c2 * MAXSEG + s2) * 128 + col];
        }
    }
    g_cat[(size_t)b * NCAT + col] = v;
}

// ---------------------------------------------------------------------------
// embed: compacted token MLP 17->256->256->128 via mma.sync
// ---------------------------------------------------------------------------
__global__ __launch_bounds__(256, 1) void embed_mma_kernel(
    const float* __restrict__ obs,
    const float* __restrict__ sb1, const float* __restrict__ sb2,
    const float* __restrict__ sb3)
{
    extern __shared__ char sm[];
    const uint32_t smu = smem_u32(sm);
    const int tid = threadIdx.x;
    const int Ntot = g_off[NB];
    const int rbase = blockIdx.x * 128;
    if (rbase >= Ntot) return;

    if (tid == 0) {
        MBAR_INIT(smu + SM_MBAR, 1);
        MBAR_INIT(smu + SM_MBAR + 8, 1);
    }
    int2 pph = make_int2(0, 0);

    // input: compacted row r -> (b, s); load obs token, split to A tiles
    if (tid < 128) {
        const int r = rbase + tid;
        float x[32];
        #pragma unroll
        for (int f = 0; f < 32; f++) x[f] = 0.f;
        if (r < Ntot) {
            int b = batch_of(r);
            int s = g_sidx[b * NS + (r - g_off[b])];
            const float* p = obs + ((size_t)b * (NS + 1) + s + 1) * NF;
            #pragma unroll
            for (int f = 0; f < NF; f++) x[f] = p[f];
        }
        #pragma unroll
        for (int c = 0; c < 32; c += 2) {
            uint32_t h, l;
            split2(x[c], x[c + 1], h, l);
            *(uint32_t*)(sm + SM_AH + tid * 528 + c * 2) = h;
            *(uint32_t*)(sm + SM_AL + tid * 528 + c * 2) = l;
        }
    }
    __syncthreads();

    float acc[32][4];
    #pragma unroll
    for (int f = 0; f < 32; f++)
        acc[f][0] = acc[f][1] = acc[f][2] = acc[f][3] = 0.f;
    layer_mma<256, 32>(sm, smu, tid, gW1h, gW1l, sb1, 256, acc, pph);
    epi_store<256>(sm, tid, acc);

    #pragma unroll
    for (int f = 0; f < 32; f++)
        acc[f][0] = acc[f][1] = acc[f][2] = acc[f][3] = 0.f;
    layer_mma<256, 256>(sm, smu, tid, gW2h, gW2l, sb2, 256, acc, pph);
    epi_store<256>(sm, tid, acc);

    #pragma unroll
    for (int f = 0; f < 16; f++)
        acc[f][0] = acc[f][1] = acc[f][2] = acc[f][3] = 0.f;
    layer_mma<128, 256>(sm, smu, tid, gW3h, gW3l, sb3, 128, acc, pph);
    epi_final(sm, tid, acc, blockIdx.x);
}

// ---------------------------------------------------------------------------
// heads: cat(137)->256->256->{23,1} via mma.sync; 128 batch rows per CTA
// ---------------------------------------------------------------------------
__device__ __forceinline__ void build_cat_A(char* sm, int tid, int rb)
{
    float* red = (float*)(sm + SM_RED);
    for (int i = tid; i < 128 * NCAT; i += 256) {
        int r = i / NCAT, c = i - r * NCAT;
        red[r * 140 + c] = g_cat[(size_t)(rb + r) * NCAT + c];
    }
    __syncthreads();
    if (tid < 128) {
        const int row = tid;
        #pragma unroll
        for (int k = 0; k < 160; k += 2) {
            float v0 = (k     < NCAT) ? red[row * 140 + k]     : 0.f;
            float v1 = (k + 1 < NCAT) ? red[row * 140 + k + 1] : 0.f;
            uint32_t h, l;
            split2(v0, v1, h, l);
            *(uint32_t*)(sm + SM_AH + row * 528 + k * 2) = h;
            *(uint32_t*)(sm + SM_AL + row * 528 + k * 2) = l;
        }
    }
    __syncthreads();
}

__global__ __launch_bounds__(256, 1) void heads_mma_kernel(
    float* __restrict__ out,
    const float* __restrict__ ab1, const float* __restrict__ ab2,
    const float* __restrict__ ab3,
    const float* __restrict__ vb1, const float* __restrict__ vb2,
    const float* __restrict__ vW3, const float* __restrict__ vb3)
{
    extern __shared__ char sm[];
    const uint32_t smu = smem_u32(sm);
    const int tid = threadIdx.x;
    const int lane = tid & 31, w = tid >> 5;
    const int rb = blockIdx.x * 128;

    if (tid == 0) {
        MBAR_INIT(smu + SM_MBAR, 1);
        MBAR_INIT(smu + SM_MBAR + 8, 1);
    }
    int2 pph = make_int2(0, 0);

    float acc[32][4];

    // ===== action branch =====
    build_cat_A(sm, tid, rb);
    #pragma unroll
    for (int f = 0; f < 32; f++)
        acc[f][0] = acc[f][1] = acc[f][2] = acc[f][3] = 0.f;
    layer_mma<256, 160>(sm, smu, tid, hA1h, hA1l, ab1, 256, acc, pph);
    epi_store<256>(sm, tid, acc);

    #pragma unroll
    for (int f = 0; f < 32; f++)
        acc[f][0] = acc[f][1] = acc[f][2] = acc[f][3] = 0.f;
    layer_mma<256, 256>(sm, smu, tid, hA2h, hA2l, ab2, 256, acc, pph);
    epi_store<256>(sm, tid, acc);

    {
        float acc3[4][4];
        #pragma unroll
        for (int f = 0; f < 4; f++)
            acc3[f][0] = acc3[f][1] = acc3[f][2] = acc3[f][3] = 0.f;
        layer_mma<32, 256>(sm, smu, tid, hA3h, hA3l, ab3, NOUT, acc3, pph);
        const float* sb = (const float*)(sm + SM_BIAS);
        const int r0 = 16 * w + (lane >> 2);
        #pragma unroll
        for (int f = 0; f < 4; f++) {
            int c = 8 * f + 2 * (lane & 3);
            if (c < NOUT) {
                out[(size_t)(rb + r0) * NOUT + c]     = acc3[f][0] + sb[c];
                out[(size_t)(rb + r0 + 8) * NOUT + c] = acc3[f][2] + sb[c];
            }
            if (c + 1 < NOUT) {
                out[(size_t)(rb + r0) * NOUT + c + 1]     = acc3[f][1] + sb[c + 1];
                out[(size_t)(rb + r0 + 8) * NOUT + c + 1] = acc3[f][3] + sb[c + 1];
            }
        }
        __syncthreads();
    }

    // ===== value branch =====
    build_cat_A(sm, tid, rb);
    #pragma unroll
    for (int f = 0; f < 32; f++)
        acc[f][0] = acc[f][1] = acc[f][2] = acc[f][3] = 0.f;
    layer_mma<256, 160>(sm, smu, tid, hV1h, hV1l, vb1, 256, acc, pph);
    epi_store<256>(sm, tid, acc);

    #pragma unroll
    for (int f = 0; f < 32; f++)
        acc[f][0] = acc[f][1] = acc[f][2] = acc[f][3] = 0.f;
    layer_mma<256, 256>(sm, smu, tid, hV2h, hV2l, vb2, 256, acc, pph);
    epi_store<256>(sm, tid, acc);

    // v3: dot(v2act, vW3) per row; 2 threads per row
    {
        float* sw = (float*)(sm + SM_BIAS);
        for (int i = tid; i < 256; i += 256) sw[i] = vW3[i];
        __syncthreads();
        const int r = tid >> 1, half = tid & 1;
        float a = 0.f;
        const char* rowp = sm + r * 528;
        #pragma unroll 4
        for (int k = half * 128; k < half * 128 + 128; k++) {
            float h = __bfloat162float(*(const __nv_bfloat16*)(rowp + SM_AH + k * 2));
            float l = __bfloat162float(*(const __nv_bfloat16*)(rowp + SM_AL + k * 2));
            a = fmaf(h + l, sw[k], a);
        }
        a += __shfl_xor_sync(0xffffffffu, a, 1);
        if (half == 0)
            out[(size_t)NB * NOUT + rb + r] = a + vb3[0];
    }
}

// ---------------------------------------------------------------------------
extern "C" void kernel_launch(void* const* d_in, const int* in_sizes, int n_in,
                              void* d_out, int out_size)
{
    const float* obs = (const float*)d_in[0];
    const float* sW1 = (const float*)d_in[1];
    const float* sb1 = (const float*)d_in[2];
    const float* sW2 = (const float*)d_in[3];
    const float* sb2 = (const float*)d_in[4];
    const float* sW3 = (const float*)d_in[5];
    const float* sb3 = (const float*)d_in[6];
    const float* aW1 = (const float*)d_in[7];
    const float* ab1 = (const float*)d_in[8];
    const float* aW2 = (const float*)d_in[9];
    const float* ab2 = (const float*)d_in[10];
    const float* aW3 = (const float*)d_in[11];
    const float* ab3 = (const float*)d_in[12];
    const float* vW1 = (const float*)d_in[13];
    const float* vb1 = (const float*)d_in[14];
    const float* vW2 = (const float*)d_in[15];
    const float* vb2 = (const float*)d_in[16];
    const float* vW3 = (const float*)d_in[17];
    const float* vb3 = (const float*)d_in[18];
    float* out = (float*)d_out;

    cudaFuncSetAttribute(embed_mma_kernel, cudaFuncAttributeMaxDynamicSharedMemorySize,
                         SM_TOTAL);
    cudaFuncSetAttribute(heads_mma_kernel, cudaFuncAttributeMaxDynamicSharedMemorySize,
                         SM_TOTAL);

    mask_kernel<<<NB, 64>>>(obs);
    scan_kernel<<<1, 1024>>>();
    prep_all<<<640, 256>>>(sW1, sW2, sW3, aW1, aW2, aW3, vW1, vW2);
    embed_mma_kernel<<<NBCTA, 256, SM_TOTAL>>>(obs, sb1, sb2, sb3);
    reduce_cat<<<NB / 2, 256>>>();
    heads_mma_kernel<<<NB / 128, 256, SM_TOTAL>>>(out, ab1, ab2, ab3,
                                                  vb1, vb2, vW3, vb3);
}

// round 14
// speedup vs baseline: 6.5926x; 1.0957x over previous
#include <cuda_runtime.h>
#include <cuda_bf16.h>
#include <cstdint>

#define NB    16384
#define NS    37
#define NF    17
#define NOWN  9
#define NH    256
#define NE    128
#define NCAT  137
#define NOUT  23

#define NBCTA 4736                       // max embed CTAs (606208 / 128)
#define MAXSEG 32

// ---------------------------------------------------------------------------
// device globals
// ---------------------------------------------------------------------------
__device__ float g_cat[(size_t)NB * NCAT];
__device__ int g_cnt[NB];
__device__ int g_off[NB + 1];
__device__ unsigned char g_sidx[NB * NS];
__device__ float g_part[(size_t)NBCTA * MAXSEG * 128];

// prepped weights, bf16 hi/lo split, layout [chunk][N rows][64B row],
// quads of each row rotated by (n>>1)&3 for conflict-free LDSM at 64B stride.
__device__ __align__(16) __nv_bfloat16 gW1h[1 * 256 * 32], gW1l[1 * 256 * 32];
__device__ __align__(16) __nv_bfloat16 gW2h[8 * 256 * 32], gW2l[8 * 256 * 32];
__device__ __align__(16) __nv_bfloat16 gW3h[8 * 128 * 32], gW3l[8 * 128 * 32];
__device__ __align__(16) __nv_bfloat16 hA1h[5 * 256 * 32], hA1l[5 * 256 * 32];
__device__ __align__(16) __nv_bfloat16 hA2h[8 * 256 * 32], hA2l[8 * 256 * 32];
__device__ __align__(16) __nv_bfloat16 hA3h[8 * 32 * 32],  hA3l[8 * 32 * 32];
__device__ __align__(16) __nv_bfloat16 hV1h[5 * 256 * 32], hV1l[5 * 256 * 32];
__device__ __align__(16) __nv_bfloat16 hV2h[8 * 256 * 32], hV2l[8 * 256 * 32];

// ---------------------------------------------------------------------------
// smem layout (bytes). A rows stride 528 (conflict-free LDSM).
// B stages are linear [hi Nn*64 | lo Nn*64], filled by cp.async.bulk.
// ---------------------------------------------------------------------------
#define SM_BIAS  0                       // 1024B
#define SM_MBAR  1536                    // 2 x 8B mbarriers
#define SM_AH    2048
#define ALOFF    67584                   // 128 * 528
#define SM_AL    (SM_AH + ALOFF)
#define SM_B0    (SM_AL + ALOFF)         // 137216 (128B aligned)
#define BSTG     32768                   // one stage (max Nn=256: 2*16KB)
#define SM_RED   SM_B0                   // alias (used only when ring drained)
#define SM_TOTAL (SM_B0 + 71680)         // 208896

// ---------------------------------------------------------------------------
// helpers
// ---------------------------------------------------------------------------
__device__ __forceinline__ uint32_t smem_u32(const void* p) {
    uint32_t a;
    asm("{ .reg .u64 t; cvta.to.shared.u64 t, %1; cvt.u32.u64 %0, t; }"
        : "=r"(a) : "l"(p));
    return a;
}

__device__ __forceinline__ void mma16816(float* d, const uint32_t* a, const uint32_t* b) {
    asm volatile(
        "mma.sync.aligned.m16n8k16.row.col.f32.bf16.bf16.f32 "
        "{%0,%1,%2,%3}, {%4,%5,%6,%7}, {%8,%9}, {%0,%1,%2,%3};"
        : "+f"(d[0]), "+f"(d[1]), "+f"(d[2]), "+f"(d[3])
        : "r"(a[0]), "r"(a[1]), "r"(a[2]), "r"(a[3]), "r"(b[0]), "r"(b[1]));
}

__device__ __forceinline__ void ldsm4(uint32_t* r, uint32_t addr) {
    asm volatile("ldmatrix.sync.aligned.m8n8.x4.shared.b16 {%0,%1,%2,%3}, [%4];"
        : "=r"(r[0]), "=r"(r[1]), "=r"(r[2]), "=r"(r[3]) : "r"(addr));
}

__device__ __forceinline__ void split2(float v0, float v1, uint32_t& h, uint32_t& l) {
    __nv_bfloat162 hh, ll;
    hh.x = __float2bfloat16(v0);
    hh.y = __float2bfloat16(v1);
    ll.x = __float2bfloat16(v0 - __bfloat162float(hh.x));
    ll.y = __float2bfloat16(v1 - __bfloat162float(hh.y));
    h = *(uint32_t*)&hh;
    l = *(uint32_t*)&ll;
}

// ubound-1 over g_off: largest b with g_off[b] <= r  (r < N_tot)
__device__ __forceinline__ int batch_of(int r) {
    int lo = 0, hi = NB + 1;
    while (lo < hi) {
        int m = (lo + hi) >> 1;
        if (__ldg(&g_off[m]) <= r) lo = m + 1; else hi = m;
    }
    return lo - 1;
}

#define MBAR_INIT(mbar, cnt) \
    asm volatile("mbarrier.init.shared.b64 [%0], %1;" :: "r"(mbar), "r"(cnt) : "memory")
#define MBAR_EXPECT_TX(mbar, tx) \
    asm volatile("mbarrier.arrive.expect_tx.shared.b64 _, [%0], %1;" \
                 :: "r"(mbar), "r"(tx) : "memory")
#define BULK_G2S(dst, src, sz, mbar) \
    asm volatile("cp.async.bulk.shared::cluster.global.mbarrier::complete_tx::bytes " \
                 "[%0], [%1], %2, [%3];" \
                 :: "r"(dst), "l"(src), "r"(sz), "r"(mbar) : "memory")

__device__ __forceinline__ void mbar_wait(uint32_t mbar, uint32_t parity) {
    asm volatile(
        "{\n\t.reg .pred P1;\n\t"
        "LAB_W_%=:\n\t"
        "mbarrier.try_wait.parity.acquire.cta.shared::cta.b64 P1, [%0], %1, 0x989680;\n\t"
        "@P1 bra LAB_D_%=;\n\t"
        "bra LAB_W_%=;\n\t"
        "LAB_D_%=:\n\t}"
        :: "r"(mbar), "r"(parity) : "memory");
}

__device__ __forceinline__ void issue_bulk(
    uint32_t smu, const __nv_bfloat16* gwh, const __nv_bfloat16* gwl,
    int chunk, int Nn, int stage)
{
    uint32_t mbar = smu + SM_MBAR + (uint32_t)stage * 8;
    uint32_t part = (uint32_t)(Nn * 64);
    MBAR_EXPECT_TX(mbar, 2 * part);
    uint32_t dst = smu + SM_B0 + (uint32_t)stage * BSTG;
    const char* sh = (const char*)gwh + (size_t)chunk * part;
    const char* sl = (const char*)gwl + (size_t)chunk * part;
    BULK_G2S(dst, sh, part, mbar);
    BULK_G2S(dst + part, sl, part, mbar);
}

// wait for global ring chunk g: stage g&1, parity (g>>1)&1
__device__ __forceinline__ void ring_wait(uint32_t smu, int g) {
    mbar_wait(smu + SM_MBAR + (uint32_t)((g & 1) * 8), (uint32_t)((g >> 1) & 1));
}

// ---------------------------------------------------------------------------
// K0: per-batch token mask -> compact local token list + count; s_own -> g_cat
// ---------------------------------------------------------------------------
__global__ void mask_kernel(const float* __restrict__ obs)
{
    const int b = blockIdx.x;
    const int tid = threadIdx.x, lane = tid & 31, warp = tid >> 5;
    __shared__ unsigned sm_m[2];

    bool nz = false;
    if (tid < NS) {
        const float* p = obs + ((size_t)b * (NS + 1) + tid + 1) * NF;
        float s = 0.f;
        #pragma unroll
        for (int f = 0; f < NF; f++) s += fabsf(p[f]);
        nz = (s != 0.f);
    }
    unsigned m = __ballot_sync(0xffffffffu, nz);
    if (lane == 0) sm_m[warp] = m;
    __syncthreads();
    if (nz) {
        int pos = __popc(m & ((1u << lane) - 1));
        if (warp == 1) pos += __popc(sm_m[0]);
        g_sidx[b * NS + pos] = (unsigned char)tid;
    }
    if (tid == 0)
        g_cnt[b] = __popc(sm_m[0]) + __popc(sm_m[1]);
    if (tid >= 48 && tid < 48 + NOWN)
        g_cat[(size_t)b * NCAT + NE + (tid - 48)] =
            obs[(size_t)b * (NS + 1) * NF + (tid - 48)];
}

// ---------------------------------------------------------------------------
// K1: exclusive scan of g_cnt -> g_off (single block, 1024 thr x 16 each)
// ---------------------------------------------------------------------------
__global__ void scan_kernel()
{
    __shared__ int sm[1024];
    const int t = threadIdx.x;
    int v[16];
    int s = 0;
    #pragma unroll
    for (int i = 0; i < 16; i++) { v[i] = s; s += g_cnt[t * 16 + i]; }
    sm[t] = s;
    __syncthreads();
    for (int d = 1; d < 1024; d <<= 1) {
        int x = (t >= d) ? sm[t - d] : 0;
        __syncthreads();
        sm[t] += x;
        __syncthreads();
    }
    int base = t ? sm[t - 1] : 0;
    #pragma unroll
    for (int i = 0; i < 16; i++) g_off[t * 16 + i] = base + v[i];
    if (t == 1023) g_off[NB] = sm[1023];
}

// ---------------------------------------------------------------------------
// prep (fused): fp32 [K][N] weights -> bf16 hi/lo [chunk][n][64B], quad-rotated
// ---------------------------------------------------------------------------
__global__ void prep_all(const float* __restrict__ sW1, const float* __restrict__ sW2,
                         const float* __restrict__ sW3, const float* __restrict__ aW1,
                         const float* __restrict__ aW2, const float* __restrict__ aW3,
                         const float* __restrict__ vW1, const float* __restrict__ vW2)
{
    const int blk = blockIdx.x;
    const float* src; __nv_bfloat16 *dh, *dl;
    int Nn, Npad, Kk, Kpad, base;
    if      (blk < 16)  { src=sW1; dh=gW1h; dl=gW1l; Nn=256;  Npad=256; Kk=NF;   Kpad=32;  base=0;   }
    else if (blk < 144) { src=sW2; dh=gW2h; dl=gW2l; Nn=256;  Npad=256; Kk=256;  Kpad=256; base=16;  }
    else if (blk < 208) { src=sW3; dh=gW3h; dl=gW3l; Nn=128;  Npad=128; Kk=256;  Kpad=256; base=144; }
    else if (blk < 288) { src=aW1; dh=hA1h; dl=hA1l; Nn=256;  Npad=256; Kk=NCAT; Kpad=160; base=208; }
    else if (blk < 416) { src=aW2; dh=hA2h; dl=hA2l; Nn=256;  Npad=256; Kk=256;  Kpad=256; base=288; }
    else if (blk < 432) { src=aW3; dh=hA3h; dl=hA3l; Nn=NOUT; Npad=32;  Kk=256;  Kpad=256; base=416; }
    else if (blk < 512) { src=vW1; dh=hV1h; dl=hV1l; Nn=256;  Npad=256; Kk=NCAT; Kpad=160; base=432; }
    else                { src=vW2; dh=hV2h; dl=hV2l; Nn=256;  Npad=256; Kk=256;  Kpad=256; base=512; }

    int idx = (blk - base) * 256 + threadIdx.x;
    int kh = Kpad >> 1;
    if (idx >= Npad * kh) return;
    int n = idx / kh, k = (idx - n * kh) * 2;
    float x0 = (n < Nn && k     < Kk) ? src[k * Nn + n]       : 0.f;
    float x1 = (n < Nn && k + 1 < Kk) ? src[(k + 1) * Nn + n] : 0.f;
    int ch = k >> 5, kk = k & 31;
    int qphys = ((kk >> 3) + ((n >> 1) & 3)) & 3;
    size_t off = (size_t)ch * Npad * 64 + (size_t)n * 64 + qphys * 16 + (kk & 7) * 2;
    __nv_bfloat162 h, l;
    h.x = __float2bfloat16(x0);
    h.y = __float2bfloat16(x1);
    l.x = __float2bfloat16(x0 - __bfloat162float(h.x));
    l.y = __float2bfloat16(x1 - __bfloat162float(h.y));
    *(__nv_bfloat162*)((char*)dh + off) = h;
    *(__nv_bfloat162*)((char*)dl + off) = l;
}

// ---------------------------------------------------------------------------
// chunk compute (512 thr, N-split): warp w -> M rows (w&7)*16, N half (w>>3)
// ---------------------------------------------------------------------------
template<int Nn>
__device__ __forceinline__ void chunk_mma(
    uint32_t smu, int tid, int kc, int stage, float (*acc)[4])
{
    constexpr int GH = Nn / 32;          // 16-wide N groups per half
    const int lane = tid & 31;
    const int w = tid >> 5;
    const int mw = w & 7, nh = w >> 3;
    const int j = lane >> 3, wi = lane & 7;
    const uint32_t aaddr = smu + SM_AH +
        (uint32_t)((16 * mw + (j & 1) * 8 + wi) * 528 + ((j >> 1) * 8) * 2 + kc * 64);
    const int nb8 = (j >> 1) * 8 + wi;
    const int rot = (nb8 >> 1) & 3;
    const uint32_t q0 = (uint32_t)((((j & 1) + rot) & 3) * 16);
    const uint32_t q1 = (uint32_t)((((j & 1) + rot + 2) & 3) * 16);
    const uint32_t bbase = smu + SM_B0 + (uint32_t)(stage * BSTG)
        + (uint32_t)((nh * (Nn / 2) + nb8) * 64);

    #pragma unroll
    for (int ks = 0; ks < 2; ks++) {
        uint32_t ah[4], al[4];
        uint32_t ao = aaddr + (uint32_t)(ks * 32);
        ldsm4(ah, ao);
        ldsm4(al, ao + ALOFF);
        const uint32_t qo = ks ? q1 : q0;
        #pragma unroll
        for (int gl = 0; gl < GH; gl++) {
            uint32_t bh[4], bl[4];
            uint32_t ba = bbase + (uint32_t)(gl * 1024) + qo;
            ldsm4(bh, ba);
            ldsm4(bl, ba + (uint32_t)(Nn * 64));
            mma16816(acc[2 * gl],     ah, bh);
            mma16816(acc[2 * gl + 1], ah, bh + 2);
            mma16816(acc[2 * gl],     ah, bl);
            mma16816(acc[2 * gl + 1], ah, bl + 2);
            mma16816(acc[2 * gl],     al, bh);
            mma16816(acc[2 * gl + 1], al, bh + 2);
        }
    }
}

// epilogue: relu(acc + bias) -> split bf16 hi/lo into A tiles (N-split)
template<int Nn>
__device__ __forceinline__ void epi_store(char* sm, int tid, float (*acc)[4])
{
    const int lane = tid & 31, w = tid >> 5;
    const int mw = w & 7, nh = w >> 3;
    const int r0 = 16 * mw + (lane >> 2);
    const int noff = nh * (Nn / 2);
    const float* sb = (const float*)(sm + SM_BIAS);
    #pragma unroll
    for (int f = 0; f < Nn / 16; f++) {
        int c = noff + 8 * f + 2 * (lane & 3);
        float b0 = sb[c], b1 = sb[c + 1];
        uint32_t h, l;
        split2(fmaxf(acc[f][0] + b0, 0.f), fmaxf(acc[f][1] + b1, 0.f), h, l);
        *(uint32_t*)(sm + SM_AH + r0 * 528 + c * 2) = h;
        *(uint32_t*)(sm + SM_AL + r0 * 528 + c * 2) = l;
        split2(fmaxf(acc[f][2] + b0, 0.f), fmaxf(acc[f][3] + b1, 0.f), h, l);
        *(uint32_t*)(sm + SM_AH + (r0 + 8) * 528 + c * 2) = h;
        *(uint32_t*)(sm + SM_AL + (r0 + 8) * 528 + c * 2) = l;
    }
    __syncthreads();
}

// embed final epilogue: relu(acc+bias) -> RED, per-segment partial sums -> g_part
__device__ __forceinline__ void epi_final(char* sm, int tid, float (*acc)[4], int cta)
{
    const int lane = tid & 31, w = tid >> 5;
    const int mw = w & 7, nh = w >> 3;
    const int r0 = 16 * mw + (lane >> 2);
    const int noff = nh * 64;
    const float* sb = (const float*)(sm + SM_BIAS);
    #pragma unroll
    for (int f = 0; f < 8; f++) {
        int c = noff + 8 * f + 2 * (lane & 3);
        float b0 = sb[c], b1 = sb[c + 1];
        float2 v;
        v.x = fmaxf(acc[f][0] + b0, 0.f);
        v.y = fmaxf(acc[f][1] + b1, 0.f);
        *(float2*)(sm + SM_RED + r0 * 528 + c * 4) = v;
        v.x = fmaxf(acc[f][2] + b0, 0.f);
        v.y = fmaxf(acc[f][3] + b1, 0.f);
        *(float2*)(sm + SM_RED + (r0 + 8) * 528 + c * 4) = v;
    }
    __syncthreads();

    const float* red = (const float*)(sm + SM_RED);
    const int Ntot = g_off[NB];
    const int rbase = cta * 128;
    int rlast = rbase + 127;
    if (rlast > Ntot - 1) rlast = Ntot - 1;
    const int bs = batch_of(rbase);
    const int be = batch_of(rlast);
    int nseg = be - bs + 1;
    if (nseg > MAXSEG) nseg = MAXSEG;
    const int grp = tid >> 7, col = tid & 127;
    for (int s2 = grp; s2 < nseg; s2 += 4) {
        int b = bs + s2;
        int lo = g_off[b];     if (lo < rbase) lo = rbase;
        int hi = g_off[b + 1]; if (hi > rbase + 128) hi = rbase + 128;
        float a = 0.f;
        for (int r = lo; r < hi; r++)
            a += red[(r - rbase) * 132 + col];
        g_part[((size_t)cta * MAXSEG + s2) * 128 + col] = a;
    }
}

// ---------------------------------------------------------------------------
// K3: per batch, add the (<=2) CTA partials -> g_cat cols 0..127
// ---------------------------------------------------------------------------
__global__ void reduce_cat()
{
    const int b = blockIdx.x * 2 + (threadIdx.x >> 7);
    const int col = threadIdx.x & 127;
    const int lo = g_off[b], hi = g_off[b + 1];
    float v = 0.f;
    if (hi > lo) {
        int c1 = lo >> 7, c2 = (hi - 1) >> 7;
        int s1 = b - batch_of(c1 << 7);
        if (s1 >= 0 && s1 < MAXSEG)
            v = g_part[((size_t)c1 * MAXSEG + s1) * 128 + col];
        if (c2 != c1) {
            int s2 = b - batch_of(c2 << 7);
            if (s2 >= 0 && s2 < MAXSEG)
                v += g_part[((size_t)c2 * MAXSEG + s2) * 128 + col];
        }
    }
    g_cat[(size_t)b * NCAT + col] = v;
}

// ---------------------------------------------------------------------------
// embed ring chunk table: g0 = W1c0; g1..8 = W2c0..7; g9..16 = W3c0..7
// ---------------------------------------------------------------------------
__device__ __forceinline__ void embed_issue(uint32_t smu, int g)
{
    if (g == 0)      issue_bulk(smu, gW1h, gW1l, 0,     256, 0);
    else if (g < 9)  issue_bulk(smu, gW2h, gW2l, g - 1, 256, g & 1);
    else             issue_bulk(smu, gW3h, gW3l, g - 9, 128, g & 1);
}

// ---------------------------------------------------------------------------
// embed: compacted token MLP 17->256->256->128 via mma.sync (512 thr)
// ---------------------------------------------------------------------------
__global__ __launch_bounds__(512, 1) void embed_mma_kernel(
    const float* __restrict__ obs,
    const float* __restrict__ sb1, const float* __restrict__ sb2,
    const float* __restrict__ sb3)
{
    extern __shared__ char sm[];
    const uint32_t smu = smem_u32(sm);
    const int tid = threadIdx.x;
    const int Ntot = g_off[NB];
    const int rbase = blockIdx.x * 128;
    if (rbase >= Ntot) return;

    if (tid == 0) {
        MBAR_INIT(smu + SM_MBAR, 1);
        MBAR_INIT(smu + SM_MBAR + 8, 1);
        embed_issue(smu, 0);
        embed_issue(smu, 1);
    }

    // input: compacted row r -> (b, s); load obs token, split to A tiles
    if (tid < 128) {
        const int r = rbase + tid;
        float x[32];
        #pragma unroll
        for (int f = 0; f < 32; f++) x[f] = 0.f;
        if (r < Ntot) {
            int b = batch_of(r);
            int s = g_sidx[b * NS + (r - g_off[b])];
            const float* p = obs + ((size_t)b * (NS + 1) + s + 1) * NF;
            #pragma unroll
            for (int f = 0; f < NF; f++) x[f] = p[f];
        }
        #pragma unroll
        for (int c = 0; c < 32; c += 2) {
            uint32_t h, l;
            split2(x[c], x[c + 1], h, l);
            *(uint32_t*)(sm + SM_AH + tid * 528 + c * 2) = h;
            *(uint32_t*)(sm + SM_AL + tid * 528 + c * 2) = l;
        }
    }
    float* sb = (float*)(sm + SM_BIAS);
    for (int i = tid; i < 256; i += 512) sb[i] = sb1[i];
    __syncthreads();

    float acc[16][4];
    #pragma unroll
    for (int f = 0; f < 16; f++)
        acc[f][0] = acc[f][1] = acc[f][2] = acc[f][3] = 0.f;

    // ---- L1 (ring chunk 0) ----
    ring_wait(smu, 0);
    chunk_mma<256>(smu, tid, 0, 0, acc);
    __syncthreads();
    if (tid == 0) embed_issue(smu, 2);
    epi_store<256>(sm, tid, acc);
    for (int i = tid; i < 256; i += 512) sb[i] = sb2[i];

    // ---- L2 (ring chunks 1..8) ----
    #pragma unroll
    for (int f = 0; f < 16; f++)
        acc[f][0] = acc[f][1] = acc[f][2] = acc[f][3] = 0.f;
    #pragma unroll 1
    for (int kc = 0; kc < 8; kc++) {
        const int g = 1 + kc;
        ring_wait(smu, g);
        chunk_mma<256>(smu, tid, kc, g & 1, acc);
        __syncthreads();
        if (tid == 0 && g + 2 <= 16) embed_issue(smu, g + 2);
    }
    epi_store<256>(sm, tid, acc);
    for (int i = tid; i < 128; i += 512) sb[i] = sb3[i];

    // ---- L3 (ring chunks 9..16) ----
    #pragma unroll
    for (int f = 0; f < 16; f++)
        acc[f][0] = acc[f][1] = acc[f][2] = acc[f][3] = 0.f;
    #pragma unroll 1
    for (int kc = 0; kc < 8; kc++) {
        const int g = 9 + kc;
        ring_wait(smu, g);
        chunk_mma<128>(smu, tid, kc, g & 1, acc);
        __syncthreads();
        if (tid == 0 && g + 2 <= 16) embed_issue(smu, g + 2);
    }
    epi_final(sm, tid, acc, blockIdx.x);
}

// ---------------------------------------------------------------------------
// heads ring table: 0-4 A1; 5-12 A2; 13-20 A3; 21-25 V1; 26-33 V2
// ---------------------------------------------------------------------------
__device__ __forceinline__ void heads_issue(uint32_t smu, int g)
{
    if (g < 5)       issue_bulk(smu, hA1h, hA1l, g,      256, g & 1);
    else if (g < 13) issue_bulk(smu, hA2h, hA2l, g - 5,  256, g & 1);
    else if (g < 21) issue_bulk(smu, hA3h, hA3l, g - 13, 32,  g & 1);
    else if (g < 26) issue_bulk(smu, hV1h, hV1l, g - 21, 256, g & 1);
    else             issue_bulk(smu, hV2h, hV2l, g - 26, 256, g & 1);
}

__device__ __forceinline__ void build_cat_A(char* sm, int tid, int rb)
{
    float* red = (float*)(sm + SM_RED);
    for (int i = tid; i < 128 * NCAT; i += 512) {
        int r = i / NCAT, c = i - r * NCAT;
        red[r * 140 + c] = g_cat[(size_t)(rb + r) * NCAT + c];
    }
    __syncthreads();
    if (tid < 128) {
        const int row = tid;
        #pragma unroll
        for (int k = 0; k < 160; k += 2) {
            float v0 = (k     < NCAT) ? red[row * 140 + k]     : 0.f;
            float v1 = (k + 1 < NCAT) ? red[row * 140 + k + 1] : 0.f;
            uint32_t h, l;
            split2(v0, v1, h, l);
            *(uint32_t*)(sm + SM_AH + row * 528 + k * 2) = h;
            *(uint32_t*)(sm + SM_AL + row * 528 + k * 2) = l;
        }
    }
    __syncthreads();
}

__global__ __launch_bounds__(512, 1) void heads_mma_kernel(
    float* __restrict__ out,
    const float* __restrict__ ab1, const float* __restrict__ ab2,
    const float* __restrict__ ab3,
    const float* __restrict__ vb1, const float* __restrict__ vb2,
    const float* __restrict__ vW3, const float* __restrict__ vb3)
{
    extern __shared__ char sm[];
    const uint32_t smu = smem_u32(sm);
    const int tid = threadIdx.x;
    const int lane = tid & 31, w = tid >> 5;
    const int mw = w & 7, nh = w >> 3;
    const int rb = blockIdx.x * 128;

    if (tid == 0) {
        MBAR_INIT(smu + SM_MBAR, 1);
        MBAR_INIT(smu + SM_MBAR + 8, 1);
    }
    float* sb = (float*)(sm + SM_BIAS);
    float acc[16][4];

    // ===== action branch =====
    build_cat_A(sm, tid, rb);          // ends with syncthreads (mbar init visible)
    if (tid == 0) { heads_issue(smu, 0); heads_issue(smu, 1); }
    for (int i = tid; i < 256; i += 512) sb[i] = ab1[i];

    #pragma unroll
    for (int f = 0; f < 16; f++)
        acc[f][0] = acc[f][1] = acc[f][2] = acc[f][3] = 0.f;
    #pragma unroll 1
    for (int kc = 0; kc < 5; kc++) {
        const int g = kc;
        ring_wait(smu, g);
        chunk_mma<256>(smu, tid, kc, g & 1, acc);
        __syncthreads();
        if (tid == 0 && g + 2 <= 20) heads_issue(smu, g + 2);
    }
    epi_store<256>(sm, tid, acc);
    for (int i = tid; i < 256; i += 512) sb[i] = ab2[i];

    #pragma unroll
    for (int f = 0; f < 16; f++)
        acc[f][0] = acc[f][1] = acc[f][2] = acc[f][3] = 0.f;
    #pragma unroll 1
    for (int kc = 0; kc < 8; kc++) {
        const int g = 5 + kc;
        ring_wait(smu, g);
        chunk_mma<256>(smu, tid, kc, g & 1, acc);
        __syncthreads();
        if (tid == 0 && g + 2 <= 20) heads_issue(smu, g + 2);
    }
    epi_store<256>(sm, tid, acc);
    for (int i = tid; i < NOUT; i += 512) sb[i] = ab3[i];

    #pragma unroll
    for (int f = 0; f < 2; f++)
        acc[f][0] = acc[f][1] = acc[f][2] = acc[f][3] = 0.f;
    #pragma unroll 1
    for (int kc = 0; kc < 8; kc++) {
        const int g = 13 + kc;
        ring_wait(smu, g);
        chunk_mma<32>(smu, tid, kc, g & 1, acc);
        __syncthreads();
        if (tid == 0 && g + 2 <= 20) heads_issue(smu, g + 2);
    }
    {
        const int r0 = 16 * mw + (lane >> 2);
        #pragma unroll
        for (int f = 0; f < 2; f++) {
            int c = nh * 16 + 8 * f + 2 * (lane & 3);
            if (c < NOUT) {
                out[(size_t)(rb + r0) * NOUT + c]     = acc[f][0] + sb[c];
                out[(size_t)(rb + r0 + 8) * NOUT + c] = acc[f][2] + sb[c];
            }
            if (c + 1 < NOUT) {
                out[(size_t)(rb + r0) * NOUT + c + 1]     = acc[f][1] + sb[c + 1];
                out[(size_t)(rb + r0 + 8) * NOUT + c + 1] = acc[f][3] + sb[c + 1];
            }
        }
        __syncthreads();
    }

    // ===== value branch =====
    build_cat_A(sm, tid, rb);          // ring drained (no issues past g20)
    if (tid == 0) { heads_issue(smu, 21); heads_issue(smu, 22); }
    for (int i = tid; i < 256; i += 512) sb[i] = vb1[i];

    #pragma unroll
    for (int f = 0; f < 16; f++)
        acc[f][0] = acc[f][1] = acc[f][2] = acc[f][3] = 0.f;
    #pragma unroll 1
    for (int kc = 0; kc < 5; kc++) {
        const int g = 21 + kc;
        ring_wait(smu, g);
        chunk_mma<256>(smu, tid, kc, g & 1, acc);
        __syncthreads();
        if (tid == 0 && g + 2 <= 33) heads_issue(smu, g + 2);
    }
    epi_store<256>(sm, tid, acc);
    for (int i = tid; i < 256; i += 512) sb[i] = vb2[i];

    #pragma unroll
    for (int f = 0; f < 16; f++)
        acc[f][0] = acc[f][1] = acc[f][2] = acc[f][3] = 0.f;
    #pragma unroll 1
    for (int kc = 0; kc < 8; kc++) {
        const int g = 26 + kc;
        ring_wait(smu, g);
        chunk_mma<256>(smu, tid, kc, g & 1, acc);
        __syncthreads();
        if (tid == 0 && g + 2 <= 33) heads_issue(smu, g + 2);
    }
    epi_store<256>(sm, tid, acc);

    // v3: dot(v2act, vW3) per row; 4 threads per row
    {
        float* sw = (float*)(sm + SM_BIAS);
        for (int i = tid; i < 256; i += 512) sw[i] = vW3[i];
        __syncthreads();
        const int r = tid >> 2, q = tid & 3;
        float a = 0.f;
        const char* rowp = sm + r * 528;
        #pragma unroll 4
        for (int k = q * 64; k < q * 64 + 64; k++) {
            float h = __bfloat162float(*(const __nv_bfloat16*)(rowp + SM_AH + k * 2));
            float l = __bfloat162float(*(const __nv_bfloat16*)(rowp + SM_AL + k * 2));
            a = fmaf(h + l, sw[k], a);
        }
        a += __shfl_xor_sync(0xffffffffu, a, 1, 4);
        a += __shfl_xor_sync(0xffffffffu, a, 2, 4);
        if (q == 0)
            out[(size_t)NB * NOUT + rb + r] = a + vb3[0];
    }
}

// ---------------------------------------------------------------------------
extern "C" void kernel_launch(void* const* d_in, const int* in_sizes, int n_in,
                              void* d_out, int out_size)
{
    const float* obs = (const float*)d_in[0];
    const float* sW1 = (const float*)d_in[1];
    const float* sb1 = (const float*)d_in[2];
    const float* sW2 = (const float*)d_in[3];
    const float* sb2 = (const float*)d_in[4];
    const float* sW3 = (const float*)d_in[5];
    const float* sb3 = (const float*)d_in[6];
    const float* aW1 = (const float*)d_in[7];
    const float* ab1 = (const float*)d_in[8];
    const float* aW2 = (const float*)d_in[9];
    const float* ab2 = (const float*)d_in[10];
    const float* aW3 = (const float*)d_in[11];
    const float* ab3 = (const float*)d_in[12];
    const float* vW1 = (const float*)d_in[13];
    const float* vb1 = (const float*)d_in[14];
    const float* vW2 = (const float*)d_in[15];
    const float* vb2 = (const float*)d_in[16];
    const float* vW3 = (const float*)d_in[17];
    const float* vb3 = (const float*)d_in[18];
    float* out = (float*)d_out;

    cudaFuncSetAttribute(embed_mma_kernel, cudaFuncAttributeMaxDynamicSharedMemorySize,
                         SM_TOTAL);
    cudaFuncSetAttribute(heads_mma_kernel, cudaFuncAttributeMaxDynamicSharedMemorySize,
                         SM_TOTAL);

    mask_kernel<<<NB, 64>>>(obs);
    scan_kernel<<<1, 1024>>>();
    prep_all<<<640, 256>>>(sW1, sW2, sW3, aW1, aW2, aW3, vW1, vW2);
    embed_mma_kernel<<<NBCTA, 512, SM_TOTAL>>>(obs, sb1, sb2, sb3);
    reduce_cat<<<NB / 2, 256>>>();
    heads_mma_kernel<<<NB / 128, 512, SM_TOTAL>>>(out, ab1, ab2, ab3,
                                                  vb1, vb2, vW3, vb3);
}

// round 16
// speedup vs baseline: 7.0518x; 1.0697x over previous
#include <cuda_runtime.h>
#include <cuda_bf16.h>
#include <cstdint>

#define NB    16384
#define NS    37
#define NF    17
#define NOWN  9
#define NH    256
#define NE    128
#define NCAT  137
#define NOUT  23

#define NBCTA 4736                       // max embed CTAs (606208 / 128)
#define MAXSEG 32

// ---------------------------------------------------------------------------
// device globals
// ---------------------------------------------------------------------------
__device__ float g_cat[(size_t)NB * NCAT];
__device__ int g_cnt[NB];
__device__ int g_off[NB + 1];
__device__ unsigned char g_sidx[NB * NS];
__device__ float g_part[(size_t)NBCTA * MAXSEG * 128];

// prepped weights, bf16 hi/lo split, layout [chunk][N rows][64B row],
// quads of each row rotated by (n>>1)&3 for conflict-free LDSM at 64B stride.
__device__ __align__(16) __nv_bfloat16 gW1h[1 * 256 * 32], gW1l[1 * 256 * 32];
__device__ __align__(16) __nv_bfloat16 gW2h[8 * 256 * 32], gW2l[8 * 256 * 32];
__device__ __align__(16) __nv_bfloat16 gW3h[8 * 128 * 32], gW3l[8 * 128 * 32];
__device__ __align__(16) __nv_bfloat16 hA1h[5 * 256 * 32], hA1l[5 * 256 * 32];
__device__ __align__(16) __nv_bfloat16 hA2h[8 * 256 * 32], hA2l[8 * 256 * 32];
__device__ __align__(16) __nv_bfloat16 hA3h[8 * 32 * 32],  hA3l[8 * 32 * 32];
__device__ __align__(16) __nv_bfloat16 hV1h[5 * 256 * 32], hV1l[5 * 256 * 32];
__device__ __align__(16) __nv_bfloat16 hV2h[8 * 256 * 32], hV2l[8 * 256 * 32];

// ---------------------------------------------------------------------------
// smem layout (bytes). A rows stride 528 (conflict-free LDSM).
// B stages are linear [hi Nn*64 | lo Nn*64], filled by cp.async.bulk.
// ---------------------------------------------------------------------------
#define SM_BIAS  0                       // 1024B
#define SM_MBAR  1536                    // 2 x 8B data mbarriers
#define SM_DONE  1552                    // 2 x 8B stage-done mbarriers (cnt 16)
#define SM_AH    2048
#define ALOFF    67584                   // 128 * 528
#define SM_AL    (SM_AH + ALOFF)
#define SM_B0    (SM_AL + ALOFF)         // 137216 (128B aligned)
#define BSTG     32768                   // one stage (max Nn=256: 2*16KB)
#define SM_RED   SM_B0                   // alias (only after full CTA sync)
#define SM_TOTAL (SM_B0 + 71680)         // 208896

// ---------------------------------------------------------------------------
// helpers
// ---------------------------------------------------------------------------
__device__ __forceinline__ uint32_t smem_u32(const void* p) {
    uint32_t a;
    asm("{ .reg .u64 t; cvta.to.shared.u64 t, %1; cvt.u32.u64 %0, t; }"
        : "=r"(a) : "l"(p));
    return a;
}

__device__ __forceinline__ void mma16816(float* d, const uint32_t* a, const uint32_t* b) {
    asm volatile(
        "mma.sync.aligned.m16n8k16.row.col.f32.bf16.bf16.f32 "
        "{%0,%1,%2,%3}, {%4,%5,%6,%7}, {%8,%9}, {%0,%1,%2,%3};"
        : "+f"(d[0]), "+f"(d[1]), "+f"(d[2]), "+f"(d[3])
        : "r"(a[0]), "r"(a[1]), "r"(a[2]), "r"(a[3]), "r"(b[0]), "r"(b[1]));
}

__device__ __forceinline__ void ldsm4(uint32_t* r, uint32_t addr) {
    asm volatile("ldmatrix.sync.aligned.m8n8.x4.shared.b16 {%0,%1,%2,%3}, [%4];"
        : "=r"(r[0]), "=r"(r[1]), "=r"(r[2]), "=r"(r[3]) : "r"(addr));
}

__device__ __forceinline__ void split2(float v0, float v1, uint32_t& h, uint32_t& l) {
    __nv_bfloat162 hh, ll;
    hh.x = __float2bfloat16(v0);
    hh.y = __float2bfloat16(v1);
    ll.x = __float2bfloat16(v0 - __bfloat162float(hh.x));
    ll.y = __float2bfloat16(v1 - __bfloat162float(hh.y));
    h = *(uint32_t*)&hh;
    l = *(uint32_t*)&ll;
}

// ubound-1 over g_off: largest b with g_off[b] <= r  (r < N_tot)
__device__ __forceinline__ int batch_of(int r) {
    int lo = 0, hi = NB + 1;
    while (lo < hi) {
        int m = (lo + hi) >> 1;
        if (__ldg(&g_off[m]) <= r) lo = m + 1; else hi = m;
    }
    return lo - 1;
}

#define MBAR_INIT(mbar, cnt) \
    asm volatile("mbarrier.init.shared.b64 [%0], %1;" :: "r"(mbar), "r"(cnt) : "memory")
#define MBAR_EXPECT_TX(mbar, tx) \
    asm volatile("mbarrier.arrive.expect_tx.shared.b64 _, [%0], %1;" \
                 :: "r"(mbar), "r"(tx) : "memory")
#define MBAR_ARRIVE(mbar) \
    asm volatile("mbarrier.arrive.shared.b64 _, [%0];" :: "r"(mbar) : "memory")
#define BULK_G2S(dst, src, sz, mbar) \
    asm volatile("cp.async.bulk.shared::cluster.global.mbarrier::complete_tx::bytes " \
                 "[%0], [%1], %2, [%3];" \
                 :: "r"(dst), "l"(src), "r"(sz), "r"(mbar) : "memory")

__device__ __forceinline__ void mbar_wait(uint32_t mbar, uint32_t parity) {
    asm volatile(
        "{\n\t.reg .pred P1;\n\t"
        "LAB_W_%=:\n\t"
        "mbarrier.try_wait.parity.acquire.cta.shared::cta.b64 P1, [%0], %1, 0x989680;\n\t"
        "@P1 bra LAB_D_%=;\n\t"
        "bra LAB_W_%=;\n\t"
        "LAB_D_%=:\n\t}"
        :: "r"(mbar), "r"(parity) : "memory");
}

__device__ __forceinline__ void issue_bulk(
    uint32_t smu, const __nv_bfloat16* gwh, const __nv_bfloat16* gwl,
    int chunk, int Nn, int stage)
{
    uint32_t mbar = smu + SM_MBAR + (uint32_t)stage * 8;
    uint32_t part = (uint32_t)(Nn * 64);
    MBAR_EXPECT_TX(mbar, 2 * part);
    uint32_t dst = smu + SM_B0 + (uint32_t)stage * BSTG;
    const char* sh = (const char*)gwh + (size_t)chunk * part;
    const char* sl = (const char*)gwl + (size_t)chunk * part;
    BULK_G2S(dst, sh, part, mbar);
    BULK_G2S(dst + part, sl, part, mbar);
}

// wait for global ring chunk g: stage g&1, parity (g>>1)&1
__device__ __forceinline__ void ring_wait(uint32_t smu, int g) {
    mbar_wait(smu + SM_MBAR + (uint32_t)((g & 1) * 8), (uint32_t)((g >> 1) & 1));
}

// consumer arrival for chunk g (one per warp)
__device__ __forceinline__ void ring_done_arrive(uint32_t smu, int g, int lane) {
    if (lane == 0) MBAR_ARRIVE(smu + SM_DONE + (uint32_t)((g & 1) * 8));
}

// producer wait: all 16 warps consumed chunk g (before reusing its stage)
__device__ __forceinline__ void ring_done_wait(uint32_t smu, int g) {
    mbar_wait(smu + SM_DONE + (uint32_t)((g & 1) * 8), (uint32_t)((g >> 1) & 1));
}

// ---------------------------------------------------------------------------
// K0: per-batch token mask -> compact local token list + count; s_own -> g_cat
// ---------------------------------------------------------------------------
__global__ void mask_kernel(const float* __restrict__ obs)
{
    const int b = blockIdx.x;
    const int tid = threadIdx.x, lane = tid & 31, warp = tid >> 5;
    __shared__ unsigned sm_m[2];

    bool nz = false;
    if (tid < NS) {
        const float* p = obs + ((size_t)b * (NS + 1) + tid + 1) * NF;
        float s = 0.f;
        #pragma unroll
        for (int f = 0; f < NF; f++) s += fabsf(p[f]);
        nz = (s != 0.f);
    }
    unsigned m = __ballot_sync(0xffffffffu, nz);
    if (lane == 0) sm_m[warp] = m;
    __syncthreads();
    if (nz) {
        int pos = __popc(m & ((1u << lane) - 1));
        if (warp == 1) pos += __popc(sm_m[0]);
        g_sidx[b * NS + pos] = (unsigned char)tid;
    }
    if (tid == 0)
        g_cnt[b] = __popc(sm_m[0]) + __popc(sm_m[1]);
    if (tid >= 48 && tid < 48 + NOWN)
        g_cat[(size_t)b * NCAT + NE + (tid - 48)] =
            obs[(size_t)b * (NS + 1) * NF + (tid - 48)];
}

// ---------------------------------------------------------------------------
// K1: exclusive scan of g_cnt -> g_off (single block, 1024 thr x 16 each)
// ---------------------------------------------------------------------------
__global__ void scan_kernel()
{
    __shared__ int sm[1024];
    const int t = threadIdx.x;
    int v[16];
    int s = 0;
    #pragma unroll
    for (int i = 0; i < 16; i++) { v[i] = s; s += g_cnt[t * 16 + i]; }
    sm[t] = s;
    __syncthreads();
    for (int d = 1; d < 1024; d <<= 1) {
        int x = (t >= d) ? sm[t - d] : 0;
        __syncthreads();
        sm[t] += x;
        __syncthreads();
    }
    int base = t ? sm[t - 1] : 0;
    #pragma unroll
    for (int i = 0; i < 16; i++) g_off[t * 16 + i] = base + v[i];
    if (t == 1023) g_off[NB] = sm[1023];
}

// ---------------------------------------------------------------------------
// prep (fused): fp32 [K][N] weights -> bf16 hi/lo [chunk][n][64B], quad-rotated
// ---------------------------------------------------------------------------
__global__ void prep_all(const float* __restrict__ sW1, const float* __restrict__ sW2,
                         const float* __restrict__ sW3, const float* __restrict__ aW1,
                         const float* __restrict__ aW2, const float* __restrict__ aW3,
                         const float* __restrict__ vW1, const float* __restrict__ vW2)
{
    const int blk = blockIdx.x;
    const float* src; __nv_bfloat16 *dh, *dl;
    int Nn, Npad, Kk, Kpad, base;
    if      (blk < 16)  { src=sW1; dh=gW1h; dl=gW1l; Nn=256;  Npad=256; Kk=NF;   Kpad=32;  base=0;   }
    else if (blk < 144) { src=sW2; dh=gW2h; dl=gW2l; Nn=256;  Npad=256; Kk=256;  Kpad=256; base=16;  }
    else if (blk < 208) { src=sW3; dh=gW3h; dl=gW3l; Nn=128;  Npad=128; Kk=256;  Kpad=256; base=144; }
    else if (blk < 288) { src=aW1; dh=hA1h; dl=hA1l; Nn=256;  Npad=256; Kk=NCAT; Kpad=160; base=208; }
    else if (blk < 416) { src=aW2; dh=hA2h; dl=hA2l; Nn=256;  Npad=256; Kk=256;  Kpad=256; base=288; }
    else if (blk < 432) { src=aW3; dh=hA3h; dl=hA3l; Nn=NOUT; Npad=32;  Kk=256;  Kpad=256; base=416; }
    else if (blk < 512) { src=vW1; dh=hV1h; dl=hV1l; Nn=256;  Npad=256; Kk=NCAT; Kpad=160; base=432; }
    else                { src=vW2; dh=hV2h; dl=hV2l; Nn=256;  Npad=256; Kk=256;  Kpad=256; base=512; }

    int idx = (blk - base) * 256 + threadIdx.x;
    int kh = Kpad >> 1;
    if (idx >= Npad * kh) return;
    int n = idx / kh, k = (idx - n * kh) * 2;
    float x0 = (n < Nn && k     < Kk) ? src[k * Nn + n]       : 0.f;
    float x1 = (n < Nn && k + 1 < Kk) ? src[(k + 1) * Nn + n] : 0.f;
    int ch = k >> 5, kk = k & 31;
    int qphys = ((kk >> 3) + ((n >> 1) & 3)) & 3;
    size_t off = (size_t)ch * Npad * 64 + (size_t)n * 64 + qphys * 16 + (kk & 7) * 2;
    __nv_bfloat162 h, l;
    h.x = __float2bfloat16(x0);
    h.y = __float2bfloat16(x1);
    l.x = __float2bfloat16(x0 - __bfloat162float(h.x));
    l.y = __float2bfloat16(x1 - __bfloat162float(h.y));
    *(__nv_bfloat162*)((char*)dh + off) = h;
    *(__nv_bfloat162*)((char*)dl + off) = l;
}

// ---------------------------------------------------------------------------
// chunk compute (512 thr, N-split): warp w -> M rows (w&7)*16, N half (w>>3)
// ---------------------------------------------------------------------------
template<int Nn>
__device__ __forceinline__ void chunk_mma(
    uint32_t smu, int tid, int kc, int stage, float (*acc)[4])
{
    constexpr int GH = Nn / 32;          // 16-wide N groups per half
    const int lane = tid & 31;
    const int w = tid >> 5;
    const int mw = w & 7, nh = w >> 3;
    const int j = lane >> 3, wi = lane & 7;
    const uint32_t aaddr = smu + SM_AH +
        (uint32_t)((16 * mw + (j & 1) * 8 + wi) * 528 + ((j >> 1) * 8) * 2 + kc * 64);
    const int nb8 = (j >> 1) * 8 + wi;
    const int rot = (nb8 >> 1) & 3;
    const uint32_t q0 = (uint32_t)((((j & 1) + rot) & 3) * 16);
    const uint32_t q1 = (uint32_t)((((j & 1) + rot + 2) & 3) * 16);
    const uint32_t bbase = smu + SM_B0 + (uint32_t)(stage * BSTG)
        + (uint32_t)((nh * (Nn / 2) + nb8) * 64);

    #pragma unroll
    for (int ks = 0; ks < 2; ks++) {
        uint32_t ah[4], al[4];
        uint32_t ao = aaddr + (uint32_t)(ks * 32);
        ldsm4(ah, ao);
        ldsm4(al, ao + ALOFF);
        const uint32_t qo = ks ? q1 : q0;
        #pragma unroll
        for (int gl = 0; gl < GH; gl++) {
            uint32_t bh[4], bl[4];
            uint32_t ba = bbase + (uint32_t)(gl * 1024) + qo;
            ldsm4(bh, ba);
            ldsm4(bl, ba + (uint32_t)(Nn * 64));
            mma16816(acc[2 * gl],     ah, bh);
            mma16816(acc[2 * gl + 1], ah, bh + 2);
            mma16816(acc[2 * gl],     ah, bl);
            mma16816(acc[2 * gl + 1], ah, bl + 2);
            mma16816(acc[2 * gl],     al, bh);
            mma16816(acc[2 * gl + 1], al, bh + 2);
        }
    }
}

// epilogue: relu(acc + bias) -> split bf16 hi/lo into A tiles (N-split)
template<int Nn>
__device__ __forceinline__ void epi_store(char* sm, int tid, float (*acc)[4])
{
    const int lane = tid & 31, w = tid >> 5;
    const int mw = w & 7, nh = w >> 3;
    const int r0 = 16 * mw + (lane >> 2);
    const int noff = nh * (Nn / 2);
    const float* sb = (const float*)(sm + SM_BIAS);
    #pragma unroll
    for (int f = 0; f < Nn / 16; f++) {
        int c = noff + 8 * f + 2 * (lane & 3);
        float b0 = sb[c], b1 = sb[c + 1];
        uint32_t h, l;
        split2(fmaxf(acc[f][0] + b0, 0.f), fmaxf(acc[f][1] + b1, 0.f), h, l);
        *(uint32_t*)(sm + SM_AH + r0 * 528 + c * 2) = h;
        *(uint32_t*)(sm + SM_AL + r0 * 528 + c * 2) = l;
        split2(fmaxf(acc[f][2] + b0, 0.f), fmaxf(acc[f][3] + b1, 0.f), h, l);
        *(uint32_t*)(sm + SM_AH + (r0 + 8) * 528 + c * 2) = h;
        *(uint32_t*)(sm + SM_AL + (r0 + 8) * 528 + c * 2) = l;
    }
    __syncthreads();
}

// embed final epilogue: relu(acc+bias) -> RED, per-segment partial sums -> g_part
// caller must __syncthreads() before (RED aliases B stages)
__device__ __forceinline__ void epi_final(char* sm, int tid, float (*acc)[4], int cta)
{
    const int lane = tid & 31, w = tid >> 5;
    const int mw = w & 7, nh = w >> 3;
    const int r0 = 16 * mw + (lane >> 2);
    const int noff = nh * 64;
    const float* sb = (const float*)(sm + SM_BIAS);
    #pragma unroll
    for (int f = 0; f < 8; f++) {
        int c = noff + 8 * f + 2 * (lane & 3);
        float b0 = sb[c], b1 = sb[c + 1];
        float2 v;
        v.x = fmaxf(acc[f][0] + b0, 0.f);
        v.y = fmaxf(acc[f][1] + b1, 0.f);
        *(float2*)(sm + SM_RED + r0 * 528 + c * 4) = v;
        v.x = fmaxf(acc[f][2] + b0, 0.f);
        v.y = fmaxf(acc[f][3] + b1, 0.f);
        *(float2*)(sm + SM_RED + (r0 + 8) * 528 + c * 4) = v;
    }
    __syncthreads();

    const float* red = (const float*)(sm + SM_RED);
    const int Ntot = g_off[NB];
    const int rbase = cta * 128;
    int rlast = rbase + 127;
    if (rlast > Ntot - 1) rlast = Ntot - 1;
    const int bs = batch_of(rbase);
    const int be = batch_of(rlast);
    int nseg = be - bs + 1;
    if (nseg > MAXSEG) nseg = MAXSEG;
    const int grp = tid >> 7, col = tid & 127;
    for (int s2 = grp; s2 < nseg; s2 += 4) {
        int b = bs + s2;
        int lo = g_off[b];     if (lo < rbase) lo = rbase;
        int hi = g_off[b + 1]; if (hi > rbase + 128) hi = rbase + 128;
        float a = 0.f;
        for (int r = lo; r < hi; r++)
            a += red[(r - rbase) * 132 + col];
        g_part[((size_t)cta * MAXSEG + s2) * 128 + col] = a;
    }
}

// ---------------------------------------------------------------------------
// K3: per batch, add the (<=2) CTA partials -> g_cat cols 0..127
// ---------------------------------------------------------------------------
__global__ void reduce_cat()
{
    const int b = blockIdx.x * 2 + (threadIdx.x >> 7);
    const int col = threadIdx.x & 127;
    const int lo = g_off[b], hi = g_off[b + 1];
    float v = 0.f;
    if (hi > lo) {
        int c1 = lo >> 7, c2 = (hi - 1) >> 7;
        int s1 = b - batch_of(c1 << 7);
        if (s1 >= 0 && s1 < MAXSEG)
            v = g_part[((size_t)c1 * MAXSEG + s1) * 128 + col];
        if (c2 != c1) {
            int s2 = b - batch_of(c2 << 7);
            if (s2 >= 0 && s2 < MAXSEG)
                v += g_part[((size_t)c2 * MAXSEG + s2) * 128 + col];
        }
    }
    g_cat[(size_t)b * NCAT + col] = v;
}

// ---------------------------------------------------------------------------
// embed ring chunk table: g0 = W1c0; g1..8 = W2c0..7; g9..16 = W3c0..7
// ---------------------------------------------------------------------------
__device__ __forceinline__ void embed_issue(uint32_t smu, int g)
{
    if (g == 0)      issue_bulk(smu, gW1h, gW1l, 0,     256, 0);
    else if (g < 9)  issue_bulk(smu, gW2h, gW2l, g - 1, 256, g & 1);
    else             issue_bulk(smu, gW3h, gW3l, g - 9, 128, g & 1);
}

// ---------------------------------------------------------------------------
// embed: compacted token MLP 17->256->256->128 via mma.sync (512 thr)
// ---------------------------------------------------------------------------
__global__ __launch_bounds__(512, 1) void embed_mma_kernel(
    const float* __restrict__ obs,
    const float* __restrict__ sb1, const float* __restrict__ sb2,
    const float* __restrict__ sb3)
{
    extern __shared__ char sm[];
    const uint32_t smu = smem_u32(sm);
    const int tid = threadIdx.x;
    const int lane = tid & 31;
    const int Ntot = g_off[NB];
    const int rbase = blockIdx.x * 128;
    if (rbase >= Ntot) return;

    if (tid == 0) {
        MBAR_INIT(smu + SM_MBAR, 1);
        MBAR_INIT(smu + SM_MBAR + 8, 1);
        MBAR_INIT(smu + SM_DONE, 16);
        MBAR_INIT(smu + SM_DONE + 8, 16);
        embed_issue(smu, 0);
        embed_issue(smu, 1);
    }

    // input: compacted row r -> (b, s); load obs token, split to A tiles
    if (tid < 128) {
        const int r = rbase + tid;
        float x[32];
        #pragma unroll
        for (int f = 0; f < 32; f++) x[f] = 0.f;
        if (r < Ntot) {
            int b = batch_of(r);
            int s = g_sidx[b * NS + (r - g_off[b])];
            const float* p = obs + ((size_t)b * (NS + 1) + s + 1) * NF;
            #pragma unroll
            for (int f = 0; f < NF; f++) x[f] = p[f];
        }
        #pragma unroll
        for (int c = 0; c < 32; c += 2) {
            uint32_t h, l;
            split2(x[c], x[c + 1], h, l);
            *(uint32_t*)(sm + SM_AH + tid * 528 + c * 2) = h;
            *(uint32_t*)(sm + SM_AL + tid * 528 + c * 2) = l;
        }
    }
    float* sb = (float*)(sm + SM_BIAS);
    for (int i = tid; i < 256; i += 512) sb[i] = sb1[i];
    __syncthreads();

    float acc[16][4];
    #pragma unroll
    for (int f = 0; f < 16; f++)
        acc[f][0] = acc[f][1] = acc[f][2] = acc[f][3] = 0.f;

    // ---- L1 (ring chunk 0) ----
    ring_wait(smu, 0);
    chunk_mma<256>(smu, tid, 0, 0, acc);
    ring_done_arrive(smu, 0, lane);
    if (tid == 0) { ring_done_wait(smu, 0); embed_issue(smu, 2); }
    __syncthreads();
    epi_store<256>(sm, tid, acc);
    for (int i = tid; i < 256; i += 512) sb[i] = sb2[i];

    // ---- L2 (ring chunks 1..8) ----
    #pragma unroll
    for (int f = 0; f < 16; f++)
        acc[f][0] = acc[f][1] = acc[f][2] = acc[f][3] = 0.f;
    #pragma unroll 1
    for (int kc = 0; kc < 8; kc++) {
        const int g = 1 + kc;
        ring_wait(smu, g);
        chunk_mma<256>(smu, tid, kc, g & 1, acc);
        ring_done_arrive(smu, g, lane);
        if (tid == 0 && g + 2 <= 16) { ring_done_wait(smu, g); embed_issue(smu, g + 2); }
    }
    __syncthreads();
    epi_store<256>(sm, tid, acc);
    for (int i = tid; i < 128; i += 512) sb[i] = sb3[i];

    // ---- L3 (ring chunks 9..16) ----
    #pragma unroll
    for (int f = 0; f < 16; f++)
        acc[f][0] = acc[f][1] = acc[f][2] = acc[f][3] = 0.f;
    #pragma unroll 1
    for (int kc = 0; kc < 8; kc++) {
        const int g = 9 + kc;
        ring_wait(smu, g);
        chunk_mma<128>(smu, tid, kc, g & 1, acc);
        ring_done_arrive(smu, g, lane);
        if (tid == 0 && g + 2 <= 16) { ring_done_wait(smu, g); embed_issue(smu, g + 2); }
    }
    __syncthreads();   // B stages drained before RED alias writes
    epi_final(sm, tid, acc, blockIdx.x);
}

// ---------------------------------------------------------------------------
// heads ring table: 0-4 A1; 5-12 A2; 13-20 A3; 21-25 V1; 26-33 V2
// ---------------------------------------------------------------------------
__device__ __forceinline__ void heads_issue(uint32_t smu, int g)
{
    if (g < 5)       issue_bulk(smu, hA1h, hA1l, g,      256, g & 1);
    else if (g < 13) issue_bulk(smu, hA2h, hA2l, g - 5,  256, g & 1);
    else if (g < 21) issue_bulk(smu, hA3h, hA3l, g - 13, 32,  g & 1);
    else if (g < 26) issue_bulk(smu, hV1h, hV1l, g - 21, 256, g & 1);
    else             issue_bulk(smu, hV2h, hV2l, g - 26, 256, g & 1);
}

__device__ __forceinline__ void build_cat_A(char* sm, int tid, int rb)
{
    float* red = (float*)(sm + SM_RED);
    for (int i = tid; i < 128 * NCAT; i += 512) {
        int r = i / NCAT, c = i - r * NCAT;
        red[r * 140 + c] = g_cat[(size_t)(rb + r) * NCAT + c];
    }
    __syncthreads();
    if (tid < 128) {
        const int row = tid;
        #pragma unroll
        for (int k = 0; k < 160; k += 2) {
            float v0 = (k     < NCAT) ? red[row * 140 + k]     : 0.f;
            float v1 = (k + 1 < NCAT) ? red[row * 140 + k + 1] : 0.f;
            uint32_t h, l;
            split2(v0, v1, h, l);
            *(uint32_t*)(sm + SM_AH + row * 528 + k * 2) = h;
            *(uint32_t*)(sm + SM_AL + row * 528 + k * 2) = l;
        }
    }
    __syncthreads();
}

__global__ __launch_bounds__(512, 1) void heads_mma_kernel(
    float* __restrict__ out,
    const float* __restrict__ ab1, const float* __restrict__ ab2,
    const float* __restrict__ ab3,
    const float* __restrict__ vb1, const float* __restrict__ vb2,
    const float* __restrict__ vW3, const float* __restrict__ vb3)
{
    extern __shared__ char sm[];
    const uint32_t smu = smem_u32(sm);
    const int tid = threadIdx.x;
    const int lane = tid & 31, w = tid >> 5;
    const int mw = w & 7, nh = w >> 3;
    const int rb = blockIdx.x * 128;

    if (tid == 0) {
        MBAR_INIT(smu + SM_MBAR, 1);
        MBAR_INIT(smu + SM_MBAR + 8, 1);
        MBAR_INIT(smu + SM_DONE, 16);
        MBAR_INIT(smu + SM_DONE + 8, 16);
    }
    float* sb = (float*)(sm + SM_BIAS);
    float acc[16][4];

    // ===== action branch =====
    build_cat_A(sm, tid, rb);          // syncs make mbar init visible
    if (tid == 0) { heads_issue(smu, 0); heads_issue(smu, 1); }
    for (int i = tid; i < 256; i += 512) sb[i] = ab1[i];

    #pragma unroll
    for (int f = 0; f < 16; f++)
        acc[f][0] = acc[f][1] = acc[f][2] = acc[f][3] = 0.f;
    #pragma unroll 1
    for (int kc = 0; kc < 5; kc++) {
        const int g = kc;
        ring_wait(smu, g);
        chunk_mma<256>(smu, tid, kc, g & 1, acc);
        ring_done_arrive(smu, g, lane);
        if (tid == 0 && g + 2 <= 20) { ring_done_wait(smu, g); heads_issue(smu, g + 2); }
    }
    __syncthreads();
    epi_store<256>(sm, tid, acc);
    for (int i = tid; i < 256; i += 512) sb[i] = ab2[i];

    #pragma unroll
    for (int f = 0; f < 16; f++)
        acc[f][0] = acc[f][1] = acc[f][2] = acc[f][3] = 0.f;
    #pragma unroll 1
    for (int kc = 0; kc < 8; kc++) {
        const int g = 5 + kc;
        ring_wait(smu, g);
        chunk_mma<256>(smu, tid, kc, g & 1, acc);
        ring_done_arrive(smu, g, lane);
        if (tid == 0 && g + 2 <= 20) { ring_done_wait(smu, g); heads_issue(smu, g + 2); }
    }
    __syncthreads();
    epi_store<256>(sm, tid, acc);
    for (int i = tid; i < NOUT; i += 512) sb[i] = ab3[i];

    #pragma unroll
    for (int f = 0; f < 2; f++)
        acc[f][0] = acc[f][1] = acc[f][2] = acc[f][3] = 0.f;
    #pragma unroll 1
    for (int kc = 0; kc < 8; kc++) {
        const int g = 13 + kc;
        ring_wait(smu, g);
        chunk_mma<32>(smu, tid, kc, g & 1, acc);
        ring_done_arrive(smu, g, lane);
        if (tid == 0 && g + 2 <= 20) { ring_done_wait(smu, g); heads_issue(smu, g + 2); }
    }
    {
        const int r0 = 16 * mw + (lane >> 2);
        #pragma unroll
        for (int f = 0; f < 2; f++) {
            int c = nh * 16 + 8 * f + 2 * (lane & 3);
            if (c < NOUT) {
                out[(size_t)(rb + r0) * NOUT + c]     = acc[f][0] + sb[c];
                out[(size_t)(rb + r0 + 8) * NOUT + c] = acc[f][2] + sb[c];
            }
            if (c + 1 < NOUT) {
                out[(size_t)(rb + r0) * NOUT + c + 1]     = acc[f][1] + sb[c + 1];
                out[(size_t)(rb + r0 + 8) * NOUT + c + 1] = acc[f][3] + sb[c + 1];
            }
        }
        __syncthreads();   // B stages drained before RED alias in build_cat_A
    }

    // ===== value branch =====
    build_cat_A(sm, tid, rb);
    if (tid == 0) { heads_issue(smu, 21); heads_issue(smu, 22); }
    for (int i = tid; i < 256; i += 512) sb[i] = vb1[i];

    #pragma unroll
    for (int f = 0; f < 16; f++)
        acc[f][0] = acc[f][1] = acc[f][2] = acc[f][3] = 0.f;
    #pragma unroll 1
    for (int kc = 0; kc < 5; kc++) {
        const int g = 21 + kc;
        ring_wait(smu, g);
        chunk_mma<256>(smu, tid, kc, g & 1, acc);
        ring_done_arrive(smu, g, lane);
        if (tid == 0 && g + 2 <= 33) { ring_done_wait(smu, g); heads_issue(smu, g + 2); }
    }
    __syncthreads();
    epi_store<256>(sm, tid, acc);
    for (int i = tid; i < 256; i += 512) sb[i] = vb2[i];

    #pragma unroll
    for (int f = 0; f < 16; f++)
        acc[f][0] = acc[f][1] = acc[f][2] = acc[f][3] = 0.f;
    #pragma unroll 1
    for (int kc = 0; kc < 8; kc++) {
        const int g = 26 + kc;
        ring_wait(smu, g);
        chunk_mma<256>(smu, tid, kc, g & 1, acc);
        ring_done_arrive(smu, g, lane);
        if (tid == 0 && g + 2 <= 33) { ring_done_wait(smu, g); heads_issue(smu, g + 2); }
    }
    __syncthreads();
    epi_store<256>(sm, tid, acc);

    // v3: dot(v2act, vW3) per row; 4 threads per row
    {
        float* sw = (float*)(sm + SM_BIAS);
        for (int i = tid; i < 256; i += 512) sw[i] = vW3[i];
        __syncthreads();
        const int r = tid >> 2, q = tid & 3;
        float a = 0.f;
        const char* rowp = sm + r * 528;
        #pragma unroll 4
        for (int k = q * 64; k < q * 64 + 64; k++) {
            float h = __bfloat162float(*(const __nv_bfloat16*)(rowp + SM_AH + k * 2));
            float l = __bfloat162float(*(const __nv_bfloat16*)(rowp + SM_AL + k * 2));
            a = fmaf(h + l, sw[k], a);
        }
        a += __shfl_xor_sync(0xffffffffu, a, 1, 4);
        a += __shfl_xor_sync(0xffffffffu, a, 2, 4);
        if (q == 0)
            out[(size_t)NB * NOUT + rb + r] = a + vb3[0];
    }
}

// ---------------------------------------------------------------------------
extern "C" void kernel_launch(void* const* d_in, const int* in_sizes, int n_in,
                              void* d_out, int out_size)
{
    const float* obs = (const float*)d_in[0];
    const float* sW1 = (const float*)d_in[1];
    const float* sb1 = (const float*)d_in[2];
    const float* sW2 = (const float*)d_in[3];
    const float* sb2 = (const float*)d_in[4];
    const float* sW3 = (const float*)d_in[5];
    const float* sb3 = (const float*)d_in[6];
    const float* aW1 = (const float*)d_in[7];
    const float* ab1 = (const float*)d_in[8];
    const float* aW2 = (const float*)d_in[9];
    const float* ab2 = (const float*)d_in[10];
    const float* aW3 = (const float*)d_in[11];
    const float* ab3 = (const float*)d_in[12];
    const float* vW1 = (const float*)d_in[13];
    const float* vb1 = (const float*)d_in[14];
    const float* vW2 = (const float*)d_in[15];
    const float* vb2 = (const float*)d_in[16];
    const float* vW3 = (const float*)d_in[17];
    const float* vb3 = (const float*)d_in[18];
    float* out = (float*)d_out;

    cudaFuncSetAttribute(embed_mma_kernel, cudaFuncAttributeMaxDynamicSharedMemorySize,
                         SM_TOTAL);
    cudaFuncSetAttribute(heads_mma_kernel, cudaFuncAttributeMaxDynamicSharedMemorySize,
                         SM_TOTAL);

    mask_kernel<<<NB, 64>>>(obs);
    scan_kernel<<<1, 1024>>>();
    prep_all<<<640, 256>>>(sW1, sW2, sW3, aW1, aW2, aW3, vW1, vW2);
    embed_mma_kernel<<<NBCTA, 512, SM_TOTAL>>>(obs, sb1, sb2, sb3);
    reduce_cat<<<NB / 2, 256>>>();
    heads_mma_kernel<<<NB / 128, 512, SM_TOTAL>>>(out, ab1, ab2, ab3,
                                                  vb1, vb2, vW3, vb3);
}